// round 9
// baseline (speedup 1.0000x reference)
#include <cuda_runtime.h>
#include <math.h>
#include <stdint.h>

#define D1 256
#define C2 40
#define MAXN 50176
#define MAXE 800000
#define MAXET (MAXE + MAXN)

// ---------------- static scratch (no runtime allocation) ----------------
__device__ float g_xl1[(size_t)MAXN * D1];
__device__ float g_xr1[(size_t)MAXN * D1];
__device__ float g_h1 [(size_t)MAXN * D1];
__device__ float g_xl2[(size_t)MAXN * C2];
__device__ float g_xr2[(size_t)MAXN * C2];
__device__ int   g_counts[MAXN + 1];
__device__ int   g_offs  [MAXN + 1];
__device__ int   g_cursor[MAXN + 1];
__device__ int   g_src[MAXET];
__device__ float g_bn[512];
__device__ float g_bns[256];
__device__ float g_bnt[256];
__device__ float g_W1[128 * 512];   // [Wl1 | Wr1]
__device__ float g_W2[256 * 80];    // [Wl2 | Wr2]

__device__ __forceinline__ uint32_t f2tf32(float f) {
    uint32_t r;
    asm("cvt.rna.tf32.f32 %0, %1;" : "=r"(r) : "f"(f));
    return r;
}

__device__ __forceinline__ void mma_tf32(float c[4], const uint32_t a[4],
                                         uint32_t b0, uint32_t b1) {
    asm volatile(
        "mma.sync.aligned.m16n8k8.row.col.f32.tf32.tf32.f32 "
        "{%0,%1,%2,%3}, {%4,%5,%6,%7}, {%8,%9}, {%0,%1,%2,%3};"
        : "+f"(c[0]), "+f"(c[1]), "+f"(c[2]), "+f"(c[3])
        : "r"(a[0]), "r"(a[1]), "r"(a[2]), "r"(a[3]), "r"(b0), "r"(b1));
}

// ---------------- zero counts + bn accumulators ----------------
__global__ void k_zero(int n) {
    int i = blockIdx.x * blockDim.x + threadIdx.x;
    if (i <= n) g_counts[i] = 0;
    if (i < 512) g_bn[i] = 0.f;
}

// ---------------- CSR build (4-edge ILP, guarded) ----------------
__global__ void k_count(const int* __restrict__ ei, int E, int N, int G) {
    int t = blockIdx.x * blockDim.x + threadIdx.x;
    if (t >= G) return;               // guard: avoid tail threads duplicating work
    int ET = E + N;
#pragma unroll
    for (int q = 0; q < 4; q++) {
        int i = t + q * G;
        if (i < ET) {
            int dst = (i < E) ? ei[E + i] : (i - E);
            atomicAdd(&g_counts[dst], 1);
        }
    }
}

__global__ void k_scan(int n) {
    __shared__ int wsum[32];
    __shared__ int s_carry;
    int t = threadIdx.x, lane = t & 31, w = t >> 5;
    if (t == 0) s_carry = 0;
    __syncthreads();
    for (int base = 0; base < n; base += 1024) {
        int v = (base + t < n) ? g_counts[base + t] : 0;
        int s = v;
#pragma unroll
        for (int o = 1; o < 32; o <<= 1) {
            int y = __shfl_up_sync(0xffffffffu, s, o);
            if (lane >= o) s += y;
        }
        if (lane == 31) wsum[w] = s;
        __syncthreads();
        if (w == 0) {
            int ws = wsum[lane];
#pragma unroll
            for (int o = 1; o < 32; o <<= 1) {
                int y = __shfl_up_sync(0xffffffffu, ws, o);
                if (lane >= o) ws += y;
            }
            wsum[lane] = ws;
        }
        __syncthreads();
        int excl = s_carry + (w > 0 ? wsum[w - 1] : 0) + s - v;
        if (base + t < n) { g_offs[base + t] = excl; g_cursor[base + t] = excl; }
        int total = wsum[31];
        __syncthreads();
        if (t == 0) s_carry += total;
        __syncthreads();
    }
    if (t == 0) g_offs[n] = s_carry;
}

__global__ void k_fill(const int* __restrict__ ei, int E, int N, int G) {
    int t = blockIdx.x * blockDim.x + threadIdx.x;
    if (t >= G) return;               // guard: avoid tail threads duplicating work
    int ET = E + N;
#pragma unroll
    for (int q = 0; q < 4; q++) {
        int i = t + q * G;
        if (i < ET) {
            int src, dst;
            if (i < E) { src = ei[i]; dst = ei[E + i]; } else { src = dst = i - E; }
            int p = atomicAdd(&g_cursor[dst], 1);
            g_src[p] = src;
        }
    }
}

// ---------------- weight concat ----------------
__global__ void k_w1cat(const float* __restrict__ Wl1, const float* __restrict__ Wr1) {
    int i = blockIdx.x * blockDim.x + threadIdx.x;
    if (i >= 128 * 512) return;
    int k = i >> 9, c = i & 511;
    g_W1[i] = (c < 256) ? Wl1[k * 256 + c] : Wr1[k * 256 + (c - 256)];
}

__global__ void k_w2cat(const float* __restrict__ Wl2, const float* __restrict__ Wr2) {
    int i = blockIdx.x * blockDim.x + threadIdx.x;
    if (i >= 256 * 80) return;
    int k = i / 80, c = i % 80;
    g_W2[i] = (c < 40) ? Wl2[k * 40 + c] : Wr2[k * 40 + (c - 40)];
}

// ---------------- layer-1 tf32 tensor-core GEMM ----------------
#define SA1 36
#define SB1 136
__global__ __launch_bounds__(256) void k_gemm1_tc(
    const float* __restrict__ A, float* __restrict__ outL,
    float* __restrict__ outR, int M)
{
    __shared__ uint32_t As[128 * SA1];
    __shared__ uint32_t Bs[32 * SB1];
    int tid = threadIdx.x;
    int lane = tid & 31, wid = tid >> 5;
    int warp_m = wid >> 1, warp_n = wid & 1;
    int m0 = blockIdx.y * 128, n0 = blockIdx.x * 128;
    float acc[2][8][4] = {};

    for (int k0 = 0; k0 < 128; k0 += 32) {
#pragma unroll
        for (int i = 0; i < 4; i++) {
            int f = tid + i * 256;
            int r = f >> 3, c4 = (f & 7) * 4;
            int gr = m0 + r;
            float4 v = make_float4(0.f, 0.f, 0.f, 0.f);
            if (gr < M) v = *(const float4*)&A[(size_t)gr * 128 + k0 + c4];
            uint4 u = make_uint4(f2tf32(v.x), f2tf32(v.y), f2tf32(v.z), f2tf32(v.w));
            *(uint4*)&As[r * SA1 + c4] = u;
        }
#pragma unroll
        for (int i = 0; i < 4; i++) {
            int f = tid + i * 256;
            int k = f >> 5, n4 = (f & 31) * 4;
            float4 v = *(const float4*)&g_W1[(size_t)(k0 + k) * 512 + n0 + n4];
            uint4 u = make_uint4(f2tf32(v.x), f2tf32(v.y), f2tf32(v.z), f2tf32(v.w));
            *(uint4*)&Bs[k * SB1 + n4] = u;
        }
        __syncthreads();
#pragma unroll
        for (int ks = 0; ks < 4; ks++) {
            int kc = ks * 8 + (lane & 3);
            uint32_t a[2][4];
            int r0 = warp_m * 32 + (lane >> 2);
#pragma unroll
            for (int mi = 0; mi < 2; mi++) {
                int r = r0 + mi * 16;
                a[mi][0] = As[r * SA1 + kc];
                a[mi][1] = As[(r + 8) * SA1 + kc];
                a[mi][2] = As[r * SA1 + kc + 4];
                a[mi][3] = As[(r + 8) * SA1 + kc + 4];
            }
#pragma unroll
            for (int nj = 0; nj < 8; nj++) {
                int n = warp_n * 64 + nj * 8 + (lane >> 2);
                uint32_t b0 = Bs[kc * SB1 + n];
                uint32_t b1 = Bs[(kc + 4) * SB1 + n];
                mma_tf32(acc[0][nj], a[0], b0, b1);
                mma_tf32(acc[1][nj], a[1], b0, b1);
            }
        }
        __syncthreads();
    }

    float* O = (n0 < 256) ? outL : outR;
    int nb = n0 & 255;
#pragma unroll
    for (int mi = 0; mi < 2; mi++) {
        int r = m0 + warp_m * 32 + mi * 16 + (lane >> 2);
#pragma unroll
        for (int nj = 0; nj < 8; nj++) {
            int nc = nb + warp_n * 64 + nj * 8 + (lane & 3) * 2;
            if (r < M)
                *(float2*)&O[(size_t)r * 256 + nc] = make_float2(acc[mi][nj][0], acc[mi][nj][1]);
            if (r + 8 < M)
                *(float2*)&O[(size_t)(r + 8) * 256 + nc] = make_float2(acc[mi][nj][2], acc[mi][nj][3]);
        }
    }
}

// ---------------- layer-1 fused attention + BN-stat accumulation ----------------
// warp per dst node; lane covers channels lane*8..lane*8+7 (head = lane>>3)
__global__ __launch_bounds__(256) void k_attn1(const float* __restrict__ att,
                                               const float* __restrict__ b1, int N)
{
    __shared__ float sh_sum[256];
    __shared__ float sh_sq[256];
    int tid = threadIdx.x;
    sh_sum[tid] = 0.f;
    sh_sq[tid] = 0.f;
    __syncthreads();

    int gt = blockIdx.x * blockDim.x + tid;
    int w = gt >> 5, lane = gt & 31;

    if (w < N) {
        int beg = g_offs[w], end = g_offs[w + 1];

        const float4* pxr = (const float4*)g_xr1 + (size_t)w * 64 + lane * 2;
        float4 r0 = pxr[0], r1 = pxr[1];
        const float4* pa = (const float4*)att + lane * 2;
        float4 at0 = pa[0], at1 = pa[1];

        float mx = -1e30f, dn = 0.f;
        float c[8] = {};

        for (int p = beg; p < end; p++) {
            int src = g_src[p];
            const float4* pl = (const float4*)g_xl1 + (size_t)src * 64 + lane * 2;
            float4 a0 = pl[0], a1 = pl[1];
            float v, s = 0.f;
            v = a0.x + r0.x; s += fmaxf(v, 0.2f * v) * at0.x;
            v = a0.y + r0.y; s += fmaxf(v, 0.2f * v) * at0.y;
            v = a0.z + r0.z; s += fmaxf(v, 0.2f * v) * at0.z;
            v = a0.w + r0.w; s += fmaxf(v, 0.2f * v) * at0.w;
            v = a1.x + r1.x; s += fmaxf(v, 0.2f * v) * at1.x;
            v = a1.y + r1.y; s += fmaxf(v, 0.2f * v) * at1.y;
            v = a1.z + r1.z; s += fmaxf(v, 0.2f * v) * at1.z;
            v = a1.w + r1.w; s += fmaxf(v, 0.2f * v) * at1.w;
            s += __shfl_xor_sync(0xffffffffu, s, 4);
            s += __shfl_xor_sync(0xffffffffu, s, 2);
            s += __shfl_xor_sync(0xffffffffu, s, 1);
            float mnew = fmaxf(mx, s);
            float sc = __expf(mx - mnew);
            float a = __expf(s - mnew);
            dn = dn * sc + a;
            c[0] = c[0] * sc + a * a0.x; c[1] = c[1] * sc + a * a0.y;
            c[2] = c[2] * sc + a * a0.z; c[3] = c[3] * sc + a * a0.w;
            c[4] = c[4] * sc + a * a1.x; c[5] = c[5] * sc + a * a1.y;
            c[6] = c[6] * sc + a * a1.z; c[7] = c[7] * sc + a * a1.w;
            mx = mnew;
        }
        float inv = 1.f / (dn + 1e-16f);
        const float4* pb = (const float4*)b1 + lane * 2;
        float4 bb0 = pb[0], bb1 = pb[1];
        float o[8];
        o[0] = c[0] * inv + bb0.x; o[1] = c[1] * inv + bb0.y;
        o[2] = c[2] * inv + bb0.z; o[3] = c[3] * inv + bb0.w;
        o[4] = c[4] * inv + bb1.x; o[5] = c[5] * inv + bb1.y;
        o[6] = c[6] * inv + bb1.z; o[7] = c[7] * inv + bb1.w;
        ((float4*)g_h1)[(size_t)w * 64 + lane * 2 + 0] =
            make_float4(o[0], o[1], o[2], o[3]);
        ((float4*)g_h1)[(size_t)w * 64 + lane * 2 + 1] =
            make_float4(o[4], o[5], o[6], o[7]);
        int cbase = lane * 8;
#pragma unroll
        for (int j = 0; j < 8; j++) {
            atomicAdd(&sh_sum[cbase + j], o[j]);
            atomicAdd(&sh_sq[cbase + j], o[j] * o[j]);
        }
    }
    __syncthreads();
    atomicAdd(&g_bn[tid], sh_sum[tid]);
    atomicAdd(&g_bn[256 + tid], sh_sq[tid]);
}

__global__ void k_bnfin(const float* __restrict__ gamma,
                        const float* __restrict__ beta, int N)
{
    int c = threadIdx.x;
    float invN = 1.f / (float)N;
    float mu = g_bn[c] * invN;
    float var = g_bn[256 + c] * invN - mu * mu;
    float rs = rsqrtf(var + 1e-5f);
    float s = gamma[c] * rs;
    g_bns[c] = s;
    g_bnt[c] = beta[c] - s * mu;
}

// ---------------- layer-2 fused BN+ELU + tf32 GEMM ----------------
#define SA2 36
#define SB2 88
__global__ __launch_bounds__(256) void k_gemm2_tc(float* __restrict__ xl2,
                                                  float* __restrict__ xr2, int M)
{
    __shared__ uint32_t As[128 * SA2];
    __shared__ uint32_t Bs[32 * SB2];
    int tid = threadIdx.x;
    int lane = tid & 31, wid = tid >> 5;
    int m0 = blockIdx.x * 128;
    float acc[10][4] = {};

    for (int k0 = 0; k0 < 256; k0 += 32) {
#pragma unroll
        for (int i = 0; i < 4; i++) {
            int f = tid + i * 256;
            int r = f >> 3, c4 = (f & 7) * 4;
            int gr = m0 + r;
            float4 v = make_float4(0.f, 0.f, 0.f, 0.f);
            if (gr < M) v = *(const float4*)&g_h1[(size_t)gr * 256 + k0 + c4];
            float4 s4 = *(const float4*)&g_bns[k0 + c4];
            float4 t4 = *(const float4*)&g_bnt[k0 + c4];
            float e0 = s4.x * v.x + t4.x; e0 = e0 > 0.f ? e0 : (__expf(e0) - 1.f);
            float e1 = s4.y * v.y + t4.y; e1 = e1 > 0.f ? e1 : (__expf(e1) - 1.f);
            float e2 = s4.z * v.z + t4.z; e2 = e2 > 0.f ? e2 : (__expf(e2) - 1.f);
            float e3 = s4.w * v.w + t4.w; e3 = e3 > 0.f ? e3 : (__expf(e3) - 1.f);
            uint4 u = make_uint4(f2tf32(e0), f2tf32(e1), f2tf32(e2), f2tf32(e3));
            *(uint4*)&As[r * SA2 + c4] = u;
        }
#pragma unroll
        for (int i = 0; i < 3; i++) {
            int f = tid + i * 256;
            if (f < 640) {
                int k = f / 20, n4 = (f % 20) * 4;
                float4 v = *(const float4*)&g_W2[(size_t)(k0 + k) * 80 + n4];
                uint4 u = make_uint4(f2tf32(v.x), f2tf32(v.y), f2tf32(v.z), f2tf32(v.w));
                *(uint4*)&Bs[k * SB2 + n4] = u;
            }
        }
        __syncthreads();
#pragma unroll
        for (int ks = 0; ks < 4; ks++) {
            int kc = ks * 8 + (lane & 3);
            int r = wid * 16 + (lane >> 2);
            uint32_t a[4];
            a[0] = As[r * SA2 + kc];
            a[1] = As[(r + 8) * SA2 + kc];
            a[2] = As[r * SA2 + kc + 4];
            a[3] = As[(r + 8) * SA2 + kc + 4];
#pragma unroll
            for (int nj = 0; nj < 10; nj++) {
                int n = nj * 8 + (lane >> 2);
                uint32_t b0 = Bs[kc * SB2 + n];
                uint32_t b1 = Bs[(kc + 4) * SB2 + n];
                mma_tf32(acc[nj], a, b0, b1);
            }
        }
        __syncthreads();
    }

    int r = m0 + wid * 16 + (lane >> 2);
#pragma unroll
    for (int nj = 0; nj < 10; nj++) {
        int col = nj * 8 + (lane & 3) * 2;
        float* O  = (col < 40) ? xl2 : xr2;
        int cc = (col < 40) ? col : col - 40;
        if (r < M)
            *(float2*)&O[(size_t)r * 40 + cc] = make_float2(acc[nj][0], acc[nj][1]);
        if (r + 8 < M)
            *(float2*)&O[(size_t)(r + 8) * 40 + cc] = make_float2(acc[nj][2], acc[nj][3]);
    }
}

// ---------------- layer-2 fused single-pass online-softmax attention ----------------
__global__ __launch_bounds__(256) void k_attn2(const float* __restrict__ att2,
                                               const float* __restrict__ b2,
                                               float* __restrict__ out, int N)
{
    int gt = blockIdx.x * blockDim.x + threadIdx.x;
    int w = gt >> 5, lane = gt & 31;
    if (w >= N) return;
    int beg = g_offs[w], end = g_offs[w + 1];
    int sub = lane >> 3, l8 = lane & 7;

    float xr[5], at[5];
#pragma unroll
    for (int j = 0; j < 5; j++) {
        int c = l8 * 5 + j;
        xr[j] = g_xr2[(size_t)w * 40 + c];
        at[j] = att2[c];
    }

    float mx = -1e30f, dn = 0.f;
    float acc[5] = {};

    for (int p0 = beg; p0 < end; p0 += 4) {
        int p = p0 + sub;
        bool valid = (p < end);
        int src = g_src[valid ? p : beg];
        float xls[5];
        float s = 0.f;
#pragma unroll
        for (int j = 0; j < 5; j++) {
            xls[j] = g_xl2[(size_t)src * 40 + l8 * 5 + j];
            float v = xls[j] + xr[j];
            s += fmaxf(v, 0.2f * v) * at[j];
        }
        s += __shfl_xor_sync(0xffffffffu, s, 4);
        s += __shfl_xor_sync(0xffffffffu, s, 2);
        s += __shfl_xor_sync(0xffffffffu, s, 1);
        if (!valid) s = -1e30f;
        float mnew = fmaxf(mx, s);
        float sc = __expf(mx - mnew);
        float a  = valid ? __expf(s - mnew) : 0.f;
        dn = dn * sc + a;
#pragma unroll
        for (int j = 0; j < 5; j++) acc[j] = acc[j] * sc + a * xls[j];
        mx = mnew;
    }

#pragma unroll
    for (int off = 8; off <= 16; off <<= 1) {
        float mo  = __shfl_xor_sync(0xffffffffu, mx, off);
        float dno = __shfl_xor_sync(0xffffffffu, dn, off);
        float ao[5];
#pragma unroll
        for (int j = 0; j < 5; j++) ao[j] = __shfl_xor_sync(0xffffffffu, acc[j], off);
        float m = fmaxf(mx, mo);
        float f1 = __expf(mx - m), f2 = __expf(mo - m);
        dn = dn * f1 + dno * f2;
#pragma unroll
        for (int j = 0; j < 5; j++) acc[j] = acc[j] * f1 + ao[j] * f2;
        mx = m;
    }

    float inv = 1.f / (dn + 1e-16f);
    if (sub == 0) {
#pragma unroll
        for (int j = 0; j < 5; j++) {
            int c = l8 * 5 + j;
            out[(size_t)w * 40 + c] = acc[j] * inv + b2[c];
        }
    }
}

// ---------------- host launcher (single stream, no object creation) ----------------
extern "C" void kernel_launch(void* const* d_in, const int* in_sizes, int n_in,
                              void* d_out, int out_size)
{
    const float* x      = (const float*)d_in[0];
    const int*   ei     = (const int*)  d_in[1];
    const float* Wl1    = (const float*)d_in[2];
    const float* Wr1    = (const float*)d_in[3];
    const float* att1   = (const float*)d_in[4];
    const float* b1     = (const float*)d_in[5];
    const float* gamma1 = (const float*)d_in[6];
    const float* beta1  = (const float*)d_in[7];
    const float* Wl2    = (const float*)d_in[8];
    const float* Wr2    = (const float*)d_in[9];
    const float* att2   = (const float*)d_in[10];
    const float* b2     = (const float*)d_in[11];
    float* out = (float*)d_out;

    int N = in_sizes[0] / 128;
    int E = in_sizes[1] / 2;
    int ET = E + N;
    int G = (ET + 3) / 4;

    void *pxl1, *pxr1, *pxl2, *pxr2;
    cudaGetSymbolAddress(&pxl1, g_xl1);
    cudaGetSymbolAddress(&pxr1, g_xr1);
    cudaGetSymbolAddress(&pxl2, g_xl2);
    cudaGetSymbolAddress(&pxr2, g_xr2);

    k_zero<<<(N + 256) / 256, 256>>>(N);
    k_count<<<(G + 255) / 256, 256>>>(ei, E, N, G);
    k_scan<<<1, 1024>>>(N);
    k_fill<<<(G + 255) / 256, 256>>>(ei, E, N, G);
    k_w1cat<<<(128 * 512 + 255) / 256, 256>>>(Wl1, Wr1);
    k_w2cat<<<(256 * 80 + 255) / 256, 256>>>(Wl2, Wr2);

    dim3 g1(4, (N + 127) / 128);
    k_gemm1_tc<<<g1, 256>>>(x, (float*)pxl1, (float*)pxr1, N);

    k_attn1<<<(N + 7) / 8, 256>>>(att1, b1, N);

    k_bnfin<<<1, 256>>>(gamma1, beta1, N);

    k_gemm2_tc<<<(N + 127) / 128, 256>>>((float*)pxl2, (float*)pxr2, N);

    k_attn2<<<(N + 7) / 8, 256>>>(att2, b2, out, N);
}

// round 10
// speedup vs baseline: 1.2073x; 1.2073x over previous
#include <cuda_runtime.h>
#include <math.h>
#include <stdint.h>

#define D1 256
#define C2 40
#define MAXN 50176
#define MAXE 800000
#define MAXET (MAXE + MAXN)

// ---------------- static scratch (no runtime allocation) ----------------
__device__ float g_xl1[(size_t)MAXN * D1];
__device__ float g_xr1[(size_t)MAXN * D1];
__device__ float g_h1 [(size_t)MAXN * D1];
__device__ float g_xl2[(size_t)MAXN * C2];
__device__ float g_xr2[(size_t)MAXN * C2];
__device__ int   g_counts[MAXN + 1];
__device__ int   g_offs  [MAXN + 1];
__device__ int   g_cursor[MAXN + 1];
__device__ int   g_src[MAXET];
__device__ float g_bn[512];
__device__ float g_bns[256];
__device__ float g_bnt[256];
__device__ float g_W1[128 * 512];   // [Wl1 | Wr1]
__device__ float g_W2[256 * 80];    // [Wl2 | Wr2]

__device__ __forceinline__ uint32_t f2tf32(float f) {
    uint32_t r;
    asm("cvt.rna.tf32.f32 %0, %1;" : "=r"(r) : "f"(f));
    return r;
}

__device__ __forceinline__ void mma_tf32(float c[4], const uint32_t a[4],
                                         uint32_t b0, uint32_t b1) {
    asm volatile(
        "mma.sync.aligned.m16n8k8.row.col.f32.tf32.tf32.f32 "
        "{%0,%1,%2,%3}, {%4,%5,%6,%7}, {%8,%9}, {%0,%1,%2,%3};"
        : "+f"(c[0]), "+f"(c[1]), "+f"(c[2]), "+f"(c[3])
        : "r"(a[0]), "r"(a[1]), "r"(a[2]), "r"(a[3]), "r"(b0), "r"(b1));
}

// ---------------- zero counts + bn accumulators ----------------
__global__ void k_zero(int n) {
    int i = blockIdx.x * blockDim.x + threadIdx.x;
    if (i <= n) g_counts[i] = 0;
    if (i < 512) g_bn[i] = 0.f;
}

// ---------------- CSR build (4-edge ILP, guarded) ----------------
__global__ void k_count(const int* __restrict__ ei, int E, int N, int G) {
    int t = blockIdx.x * blockDim.x + threadIdx.x;
    if (t >= G) return;
    int ET = E + N;
#pragma unroll
    for (int q = 0; q < 4; q++) {
        int i = t + q * G;
        if (i < ET) {
            int dst = (i < E) ? ei[E + i] : (i - E);
            atomicAdd(&g_counts[dst], 1);
        }
    }
}

__global__ void k_scan(int n) {
    __shared__ int wsum[32];
    __shared__ int s_carry;
    int t = threadIdx.x, lane = t & 31, w = t >> 5;
    if (t == 0) s_carry = 0;
    __syncthreads();
    for (int base = 0; base < n; base += 1024) {
        int v = (base + t < n) ? g_counts[base + t] : 0;
        int s = v;
#pragma unroll
        for (int o = 1; o < 32; o <<= 1) {
            int y = __shfl_up_sync(0xffffffffu, s, o);
            if (lane >= o) s += y;
        }
        if (lane == 31) wsum[w] = s;
        __syncthreads();
        if (w == 0) {
            int ws = wsum[lane];
#pragma unroll
            for (int o = 1; o < 32; o <<= 1) {
                int y = __shfl_up_sync(0xffffffffu, ws, o);
                if (lane >= o) ws += y;
            }
            wsum[lane] = ws;
        }
        __syncthreads();
        int excl = s_carry + (w > 0 ? wsum[w - 1] : 0) + s - v;
        if (base + t < n) { g_offs[base + t] = excl; g_cursor[base + t] = excl; }
        int total = wsum[31];
        __syncthreads();
        if (t == 0) s_carry += total;
        __syncthreads();
    }
    if (t == 0) g_offs[n] = s_carry;
}

__global__ void k_fill(const int* __restrict__ ei, int E, int N, int G) {
    int t = blockIdx.x * blockDim.x + threadIdx.x;
    if (t >= G) return;
    int ET = E + N;
#pragma unroll
    for (int q = 0; q < 4; q++) {
        int i = t + q * G;
        if (i < ET) {
            int src, dst;
            if (i < E) { src = ei[i]; dst = ei[E + i]; } else { src = dst = i - E; }
            int p = atomicAdd(&g_cursor[dst], 1);
            g_src[p] = src;
        }
    }
}

// ---------------- weight concat ----------------
__global__ void k_w1cat(const float* __restrict__ Wl1, const float* __restrict__ Wr1) {
    int i = blockIdx.x * blockDim.x + threadIdx.x;
    if (i >= 128 * 512) return;
    int k = i >> 9, c = i & 511;
    g_W1[i] = (c < 256) ? Wl1[k * 256 + c] : Wr1[k * 256 + (c - 256)];
}

__global__ void k_w2cat(const float* __restrict__ Wl2, const float* __restrict__ Wr2) {
    int i = blockIdx.x * blockDim.x + threadIdx.x;
    if (i >= 256 * 80) return;
    int k = i / 80, c = i % 80;
    g_W2[i] = (c < 40) ? Wl2[k * 40 + c] : Wr2[k * 40 + (c - 40)];
}

// ---------------- layer-1 tf32 tensor-core GEMM ----------------
#define SA1 36
#define SB1 136
__global__ __launch_bounds__(256) void k_gemm1_tc(
    const float* __restrict__ A, float* __restrict__ outL,
    float* __restrict__ outR, int M)
{
    __shared__ uint32_t As[128 * SA1];
    __shared__ uint32_t Bs[32 * SB1];
    int tid = threadIdx.x;
    int lane = tid & 31, wid = tid >> 5;
    int warp_m = wid >> 1, warp_n = wid & 1;
    int m0 = blockIdx.y * 128, n0 = blockIdx.x * 128;
    float acc[2][8][4] = {};

    for (int k0 = 0; k0 < 128; k0 += 32) {
#pragma unroll
        for (int i = 0; i < 4; i++) {
            int f = tid + i * 256;
            int r = f >> 3, c4 = (f & 7) * 4;
            int gr = m0 + r;
            float4 v = make_float4(0.f, 0.f, 0.f, 0.f);
            if (gr < M) v = *(const float4*)&A[(size_t)gr * 128 + k0 + c4];
            uint4 u = make_uint4(f2tf32(v.x), f2tf32(v.y), f2tf32(v.z), f2tf32(v.w));
            *(uint4*)&As[r * SA1 + c4] = u;
        }
#pragma unroll
        for (int i = 0; i < 4; i++) {
            int f = tid + i * 256;
            int k = f >> 5, n4 = (f & 31) * 4;
            float4 v = *(const float4*)&g_W1[(size_t)(k0 + k) * 512 + n0 + n4];
            uint4 u = make_uint4(f2tf32(v.x), f2tf32(v.y), f2tf32(v.z), f2tf32(v.w));
            *(uint4*)&Bs[k * SB1 + n4] = u;
        }
        __syncthreads();
#pragma unroll
        for (int ks = 0; ks < 4; ks++) {
            int kc = ks * 8 + (lane & 3);
            uint32_t a[2][4];
            int r0 = warp_m * 32 + (lane >> 2);
#pragma unroll
            for (int mi = 0; mi < 2; mi++) {
                int r = r0 + mi * 16;
                a[mi][0] = As[r * SA1 + kc];
                a[mi][1] = As[(r + 8) * SA1 + kc];
                a[mi][2] = As[r * SA1 + kc + 4];
                a[mi][3] = As[(r + 8) * SA1 + kc + 4];
            }
#pragma unroll
            for (int nj = 0; nj < 8; nj++) {
                int n = warp_n * 64 + nj * 8 + (lane >> 2);
                uint32_t b0 = Bs[kc * SB1 + n];
                uint32_t b1 = Bs[(kc + 4) * SB1 + n];
                mma_tf32(acc[0][nj], a[0], b0, b1);
                mma_tf32(acc[1][nj], a[1], b0, b1);
            }
        }
        __syncthreads();
    }

    float* O = (n0 < 256) ? outL : outR;
    int nb = n0 & 255;
#pragma unroll
    for (int mi = 0; mi < 2; mi++) {
        int r = m0 + warp_m * 32 + mi * 16 + (lane >> 2);
#pragma unroll
        for (int nj = 0; nj < 8; nj++) {
            int nc = nb + warp_n * 64 + nj * 8 + (lane & 3) * 2;
            if (r < M)
                *(float2*)&O[(size_t)r * 256 + nc] = make_float2(acc[mi][nj][0], acc[mi][nj][1]);
            if (r + 8 < M)
                *(float2*)&O[(size_t)(r + 8) * 256 + nc] = make_float2(acc[mi][nj][2], acc[mi][nj][3]);
        }
    }
}

// ---------------- layer-1 fused single-pass online-softmax attention ----------------
// warp per dst node; no block sync — warps retire independently
__global__ __launch_bounds__(256) void k_attn1(const float* __restrict__ att,
                                               const float* __restrict__ b1, int N)
{
    int gt = blockIdx.x * blockDim.x + threadIdx.x;
    int w = gt >> 5, lane = gt & 31;
    if (w >= N) return;
    int beg = g_offs[w], end = g_offs[w + 1];

    const float4* pxr = (const float4*)g_xr1 + (size_t)w * 64 + lane * 2;
    float4 r0 = pxr[0], r1 = pxr[1];
    const float4* pa = (const float4*)att + lane * 2;
    float4 at0 = pa[0], at1 = pa[1];

    float mx = -1e30f, dn = 0.f;
    float c0 = 0, c1 = 0, c2 = 0, c3 = 0, c4 = 0, c5 = 0, c6 = 0, c7 = 0;

    for (int p = beg; p < end; p++) {
        int src = g_src[p];
        const float4* pl = (const float4*)g_xl1 + (size_t)src * 64 + lane * 2;
        float4 a0 = pl[0], a1 = pl[1];
        float v, s = 0.f;
        v = a0.x + r0.x; s += fmaxf(v, 0.2f * v) * at0.x;
        v = a0.y + r0.y; s += fmaxf(v, 0.2f * v) * at0.y;
        v = a0.z + r0.z; s += fmaxf(v, 0.2f * v) * at0.z;
        v = a0.w + r0.w; s += fmaxf(v, 0.2f * v) * at0.w;
        v = a1.x + r1.x; s += fmaxf(v, 0.2f * v) * at1.x;
        v = a1.y + r1.y; s += fmaxf(v, 0.2f * v) * at1.y;
        v = a1.z + r1.z; s += fmaxf(v, 0.2f * v) * at1.z;
        v = a1.w + r1.w; s += fmaxf(v, 0.2f * v) * at1.w;
        s += __shfl_xor_sync(0xffffffffu, s, 4);
        s += __shfl_xor_sync(0xffffffffu, s, 2);
        s += __shfl_xor_sync(0xffffffffu, s, 1);
        float mnew = fmaxf(mx, s);
        float sc = __expf(mx - mnew);
        float a = __expf(s - mnew);
        dn = dn * sc + a;
        c0 = c0 * sc + a * a0.x; c1 = c1 * sc + a * a0.y;
        c2 = c2 * sc + a * a0.z; c3 = c3 * sc + a * a0.w;
        c4 = c4 * sc + a * a1.x; c5 = c5 * sc + a * a1.y;
        c6 = c6 * sc + a * a1.z; c7 = c7 * sc + a * a1.w;
        mx = mnew;
    }
    float inv = 1.f / (dn + 1e-16f);
    const float4* pb = (const float4*)b1 + lane * 2;
    float4 bb0 = pb[0], bb1 = pb[1];
    ((float4*)g_h1)[(size_t)w * 64 + lane * 2 + 0] =
        make_float4(c0 * inv + bb0.x, c1 * inv + bb0.y, c2 * inv + bb0.z, c3 * inv + bb0.w);
    ((float4*)g_h1)[(size_t)w * 64 + lane * 2 + 1] =
        make_float4(c4 * inv + bb1.x, c5 * inv + bb1.y, c6 * inv + bb1.z, c7 * inv + bb1.w);
}

// ---------------- batch-norm stats (separate pass; no stragglers) ----------------
__global__ __launch_bounds__(256) void k_bnstats(int N)
{
    int c = threadIdx.x;
    int r0 = blockIdx.x * 128;
    int rend = min(r0 + 128, N);
    float s = 0.f, s2 = 0.f;
    for (int r = r0; r < rend; r++) {
        float v = g_h1[(size_t)r * 256 + c];
        s += v; s2 += v * v;
    }
    atomicAdd(&g_bn[c], s);
    atomicAdd(&g_bn[256 + c], s2);
}

__global__ void k_bnfin(const float* __restrict__ gamma,
                        const float* __restrict__ beta, int N)
{
    int c = threadIdx.x;
    float invN = 1.f / (float)N;
    float mu = g_bn[c] * invN;
    float var = g_bn[256 + c] * invN - mu * mu;
    float rs = rsqrtf(var + 1e-5f);
    float s = gamma[c] * rs;
    g_bns[c] = s;
    g_bnt[c] = beta[c] - s * mu;
}

// ---------------- layer-2 fused BN+ELU + tf32 GEMM ----------------
#define SA2 36
#define SB2 88
__global__ __launch_bounds__(256) void k_gemm2_tc(float* __restrict__ xl2,
                                                  float* __restrict__ xr2, int M)
{
    __shared__ uint32_t As[128 * SA2];
    __shared__ uint32_t Bs[32 * SB2];
    int tid = threadIdx.x;
    int lane = tid & 31, wid = tid >> 5;
    int m0 = blockIdx.x * 128;
    float acc[10][4] = {};

    for (int k0 = 0; k0 < 256; k0 += 32) {
#pragma unroll
        for (int i = 0; i < 4; i++) {
            int f = tid + i * 256;
            int r = f >> 3, c4 = (f & 7) * 4;
            int gr = m0 + r;
            float4 v = make_float4(0.f, 0.f, 0.f, 0.f);
            if (gr < M) v = *(const float4*)&g_h1[(size_t)gr * 256 + k0 + c4];
            float4 s4 = *(const float4*)&g_bns[k0 + c4];
            float4 t4 = *(const float4*)&g_bnt[k0 + c4];
            float e0 = s4.x * v.x + t4.x; e0 = e0 > 0.f ? e0 : (__expf(e0) - 1.f);
            float e1 = s4.y * v.y + t4.y; e1 = e1 > 0.f ? e1 : (__expf(e1) - 1.f);
            float e2 = s4.z * v.z + t4.z; e2 = e2 > 0.f ? e2 : (__expf(e2) - 1.f);
            float e3 = s4.w * v.w + t4.w; e3 = e3 > 0.f ? e3 : (__expf(e3) - 1.f);
            uint4 u = make_uint4(f2tf32(e0), f2tf32(e1), f2tf32(e2), f2tf32(e3));
            *(uint4*)&As[r * SA2 + c4] = u;
        }
#pragma unroll
        for (int i = 0; i < 3; i++) {
            int f = tid + i * 256;
            if (f < 640) {
                int k = f / 20, n4 = (f % 20) * 4;
                float4 v = *(const float4*)&g_W2[(size_t)(k0 + k) * 80 + n4];
                uint4 u = make_uint4(f2tf32(v.x), f2tf32(v.y), f2tf32(v.z), f2tf32(v.w));
                *(uint4*)&Bs[k * SB2 + n4] = u;
            }
        }
        __syncthreads();
#pragma unroll
        for (int ks = 0; ks < 4; ks++) {
            int kc = ks * 8 + (lane & 3);
            int r = wid * 16 + (lane >> 2);
            uint32_t a[4];
            a[0] = As[r * SA2 + kc];
            a[1] = As[(r + 8) * SA2 + kc];
            a[2] = As[r * SA2 + kc + 4];
            a[3] = As[(r + 8) * SA2 + kc + 4];
#pragma unroll
            for (int nj = 0; nj < 10; nj++) {
                int n = nj * 8 + (lane >> 2);
                uint32_t b0 = Bs[kc * SB2 + n];
                uint32_t b1 = Bs[(kc + 4) * SB2 + n];
                mma_tf32(acc[nj], a, b0, b1);
            }
        }
        __syncthreads();
    }

    int r = m0 + wid * 16 + (lane >> 2);
#pragma unroll
    for (int nj = 0; nj < 10; nj++) {
        int col = nj * 8 + (lane & 3) * 2;
        float* O  = (col < 40) ? xl2 : xr2;
        int cc = (col < 40) ? col : col - 40;
        if (r < M)
            *(float2*)&O[(size_t)r * 40 + cc] = make_float2(acc[nj][0], acc[nj][1]);
        if (r + 8 < M)
            *(float2*)&O[(size_t)(r + 8) * 40 + cc] = make_float2(acc[nj][2], acc[nj][3]);
    }
}

// ---------------- layer-2 fused single-pass online-softmax attention ----------------
__global__ __launch_bounds__(256) void k_attn2(const float* __restrict__ att2,
                                               const float* __restrict__ b2,
                                               float* __restrict__ out, int N)
{
    int gt = blockIdx.x * blockDim.x + threadIdx.x;
    int w = gt >> 5, lane = gt & 31;
    if (w >= N) return;
    int beg = g_offs[w], end = g_offs[w + 1];
    int sub = lane >> 3, l8 = lane & 7;

    float xr[5], at[5];
#pragma unroll
    for (int j = 0; j < 5; j++) {
        int c = l8 * 5 + j;
        xr[j] = g_xr2[(size_t)w * 40 + c];
        at[j] = att2[c];
    }

    float mx = -1e30f, dn = 0.f;
    float acc[5] = {};

    for (int p0 = beg; p0 < end; p0 += 4) {
        int p = p0 + sub;
        bool valid = (p < end);
        int src = g_src[valid ? p : beg];
        float xls[5];
        float s = 0.f;
#pragma unroll
        for (int j = 0; j < 5; j++) {
            xls[j] = g_xl2[(size_t)src * 40 + l8 * 5 + j];
            float v = xls[j] + xr[j];
            s += fmaxf(v, 0.2f * v) * at[j];
        }
        s += __shfl_xor_sync(0xffffffffu, s, 4);
        s += __shfl_xor_sync(0xffffffffu, s, 2);
        s += __shfl_xor_sync(0xffffffffu, s, 1);
        if (!valid) s = -1e30f;
        float mnew = fmaxf(mx, s);
        float sc = __expf(mx - mnew);
        float a  = valid ? __expf(s - mnew) : 0.f;
        dn = dn * sc + a;
#pragma unroll
        for (int j = 0; j < 5; j++) acc[j] = acc[j] * sc + a * xls[j];
        mx = mnew;
    }

#pragma unroll
    for (int off = 8; off <= 16; off <<= 1) {
        float mo  = __shfl_xor_sync(0xffffffffu, mx, off);
        float dno = __shfl_xor_sync(0xffffffffu, dn, off);
        float ao[5];
#pragma unroll
        for (int j = 0; j < 5; j++) ao[j] = __shfl_xor_sync(0xffffffffu, acc[j], off);
        float m = fmaxf(mx, mo);
        float f1 = __expf(mx - m), f2 = __expf(mo - m);
        dn = dn * f1 + dno * f2;
#pragma unroll
        for (int j = 0; j < 5; j++) acc[j] = acc[j] * f1 + ao[j] * f2;
        mx = m;
    }

    float inv = 1.f / (dn + 1e-16f);
    if (sub == 0) {
#pragma unroll
        for (int j = 0; j < 5; j++) {
            int c = l8 * 5 + j;
            out[(size_t)w * 40 + c] = acc[j] * inv + b2[c];
        }
    }
}

// ---------------- host launcher (single stream) ----------------
extern "C" void kernel_launch(void* const* d_in, const int* in_sizes, int n_in,
                              void* d_out, int out_size)
{
    const float* x      = (const float*)d_in[0];
    const int*   ei     = (const int*)  d_in[1];
    const float* Wl1    = (const float*)d_in[2];
    const float* Wr1    = (const float*)d_in[3];
    const float* att1   = (const float*)d_in[4];
    const float* b1     = (const float*)d_in[5];
    const float* gamma1 = (const float*)d_in[6];
    const float* beta1  = (const float*)d_in[7];
    const float* Wl2    = (const float*)d_in[8];
    const float* Wr2    = (const float*)d_in[9];
    const float* att2   = (const float*)d_in[10];
    const float* b2     = (const float*)d_in[11];
    float* out = (float*)d_out;

    int N = in_sizes[0] / 128;
    int E = in_sizes[1] / 2;
    int ET = E + N;
    int G = (ET + 3) / 4;

    void *pxl1, *pxr1, *pxl2, *pxr2;
    cudaGetSymbolAddress(&pxl1, g_xl1);
    cudaGetSymbolAddress(&pxr1, g_xr1);
    cudaGetSymbolAddress(&pxl2, g_xl2);
    cudaGetSymbolAddress(&pxr2, g_xr2);

    k_zero<<<(N + 256) / 256, 256>>>(N);
    k_count<<<(G + 255) / 256, 256>>>(ei, E, N, G);
    k_scan<<<1, 1024>>>(N);
    k_fill<<<(G + 255) / 256, 256>>>(ei, E, N, G);
    k_w1cat<<<(128 * 512 + 255) / 256, 256>>>(Wl1, Wr1);
    k_w2cat<<<(256 * 80 + 255) / 256, 256>>>(Wl2, Wr2);

    dim3 g1(4, (N + 127) / 128);
    k_gemm1_tc<<<g1, 256>>>(x, (float*)pxl1, (float*)pxr1, N);

    k_attn1<<<(N + 7) / 8, 256>>>(att1, b1, N);

    k_bnstats<<<(N + 127) / 128, 256>>>(N);
    k_bnfin<<<1, 256>>>(gamma1, beta1, N);

    k_gemm2_tc<<<(N + 127) / 128, 256>>>((float*)pxl2, (float*)pxr2, N);

    k_attn2<<<(N + 7) / 8, 256>>>(att2, b2, out, N);
}

// round 11
// speedup vs baseline: 1.2759x; 1.0568x over previous
#include <cuda_runtime.h>
#include <math.h>
#include <stdint.h>

#define D1 256
#define C2 40
#define MAXN 50176
#define MAXE 800000
#define MAXET (MAXE + MAXN)

// ---------------- static scratch (no runtime allocation) ----------------
__device__ float    g_xl1[(size_t)MAXN * D1];
__device__ float    g_xr1[(size_t)MAXN * D1];
__device__ float    g_h1 [(size_t)MAXN * D1];
__device__ float    g_xl2[(size_t)MAXN * C2];
__device__ float    g_xr2[(size_t)MAXN * C2];
__device__ uint32_t g_xt [(size_t)MAXN * 128];   // x pre-converted to tf32
__device__ int      g_counts[MAXN + 1];
__device__ int      g_offs  [MAXN + 1];
__device__ int      g_cursor[MAXN + 1];
__device__ int      g_src[MAXET];
__device__ float    g_bn[512];
__device__ float    g_bns[256];
__device__ float    g_bnt[256];
__device__ uint32_t g_W1t[128 * 512];   // [Wl1 | Wr1] tf32
__device__ uint32_t g_W2t[256 * 80];    // [Wl2 | Wr2] tf32

__device__ __forceinline__ uint32_t f2tf32(float f) {
    uint32_t r;
    asm("cvt.rna.tf32.f32 %0, %1;" : "=r"(r) : "f"(f));
    return r;
}

__device__ __forceinline__ void mma_tf32(float c[4], const uint32_t a[4],
                                         uint32_t b0, uint32_t b1) {
    asm volatile(
        "mma.sync.aligned.m16n8k8.row.col.f32.tf32.tf32.f32 "
        "{%0,%1,%2,%3}, {%4,%5,%6,%7}, {%8,%9}, {%0,%1,%2,%3};"
        : "+f"(c[0]), "+f"(c[1]), "+f"(c[2]), "+f"(c[3])
        : "r"(a[0]), "r"(a[1]), "r"(a[2]), "r"(a[3]), "r"(b0), "r"(b1));
}

// ---------------- zero counts + bn accumulators ----------------
__global__ void k_zero(int n) {
    int i = blockIdx.x * blockDim.x + threadIdx.x;
    if (i <= n) g_counts[i] = 0;
    if (i < 512) g_bn[i] = 0.f;
}

// ---------------- fused pre-pass: count | w1cat | w2cat | x-convert ----------------
__global__ void k_pre(const int* __restrict__ ei, int E, int N, int G,
                      int CB, int W1B, int W2B,
                      const float* __restrict__ x,
                      const float* __restrict__ Wl1, const float* __restrict__ Wr1,
                      const float* __restrict__ Wl2, const float* __restrict__ Wr2)
{
    int b = blockIdx.x, tid = threadIdx.x;
    if (b < CB) {                       // edge-count histogram (4-edge ILP, guarded)
        int t = b * 256 + tid;
        if (t >= G) return;
        int ET = E + N;
#pragma unroll
        for (int q = 0; q < 4; q++) {
            int i = t + q * G;
            if (i < ET) {
                int dst = (i < E) ? ei[E + i] : (i - E);
                atomicAdd(&g_counts[dst], 1);
            }
        }
    } else if (b < CB + W1B) {          // W1 concat + tf32 convert
        int i = (b - CB) * 256 + tid;
        int k = i >> 9, c = i & 511;
        float v = (c < 256) ? Wl1[k * 256 + c] : Wr1[k * 256 + (c - 256)];
        g_W1t[i] = f2tf32(v);
    } else if (b < CB + W1B + W2B) {    // W2 concat + tf32 convert
        int i = (b - CB - W1B) * 256 + tid;
        if (i < 256 * 80) {
            int k = i / 80, c = i % 80;
            float v = (c < 40) ? Wl2[k * 40 + c] : Wr2[k * 40 + (c - 40)];
            g_W2t[i] = f2tf32(v);
        }
    } else {                            // x -> tf32 (float4 granularity)
        int i = (b - CB - W1B - W2B) * 256 + tid;
        if (i < N * 32) {
            float4 v = ((const float4*)x)[i];
            ((uint4*)g_xt)[i] = make_uint4(f2tf32(v.x), f2tf32(v.y),
                                           f2tf32(v.z), f2tf32(v.w));
        }
    }
}

__global__ void k_scan(int n) {
    __shared__ int wsum[32];
    __shared__ int s_carry;
    int t = threadIdx.x, lane = t & 31, w = t >> 5;
    if (t == 0) s_carry = 0;
    __syncthreads();
    for (int base = 0; base < n; base += 1024) {
        int v = (base + t < n) ? g_counts[base + t] : 0;
        int s = v;
#pragma unroll
        for (int o = 1; o < 32; o <<= 1) {
            int y = __shfl_up_sync(0xffffffffu, s, o);
            if (lane >= o) s += y;
        }
        if (lane == 31) wsum[w] = s;
        __syncthreads();
        if (w == 0) {
            int ws = wsum[lane];
#pragma unroll
            for (int o = 1; o < 32; o <<= 1) {
                int y = __shfl_up_sync(0xffffffffu, ws, o);
                if (lane >= o) ws += y;
            }
            wsum[lane] = ws;
        }
        __syncthreads();
        int excl = s_carry + (w > 0 ? wsum[w - 1] : 0) + s - v;
        if (base + t < n) { g_offs[base + t] = excl; g_cursor[base + t] = excl; }
        int total = wsum[31];
        __syncthreads();
        if (t == 0) s_carry += total;
        __syncthreads();
    }
    if (t == 0) g_offs[n] = s_carry;
}

// ---------------- fused: CSR fill (blocks < FB) | layer-1 tf32 GEMM ----------------
#define SA1 36
#define SB1 136
__global__ __launch_bounds__(256, 2) void k_fill_gemm1(
    const int* __restrict__ ei, int E, int N, int G, int FB,
    float* __restrict__ outL, float* __restrict__ outR, int M)
{
    __shared__ uint32_t As[128 * SA1];
    __shared__ uint32_t Bs[32 * SB1];
    int tid = threadIdx.x;

    if (blockIdx.x < FB) {              // ---- CSR fill ----
        int t = blockIdx.x * 256 + tid;
        if (t >= G) return;
        int ET = E + N;
#pragma unroll
        for (int q = 0; q < 4; q++) {
            int i = t + q * G;
            if (i < ET) {
                int src, dst;
                if (i < E) { src = ei[i]; dst = ei[E + i]; } else { src = dst = i - E; }
                int p = atomicAdd(&g_cursor[dst], 1);
                g_src[p] = src;
            }
        }
        return;
    }

    // ---- GEMM: C[M,512] = xt[M,128] @ W1t[128,512] ----
    int flat = blockIdx.x - FB;
    int n0 = (flat & 3) << 7;
    int m0 = (flat >> 2) << 7;
    int lane = tid & 31, wid = tid >> 5;
    int warp_m = wid >> 1, warp_n = wid & 1;
    float acc[2][8][4] = {};

    for (int k0 = 0; k0 < 128; k0 += 32) {
#pragma unroll
        for (int i = 0; i < 4; i++) {
            int f = tid + i * 256;
            int r = f >> 3, c4 = (f & 7) * 4;
            // rows beyond M stay zero in g_xt (static init) — safe unguarded
            *(uint4*)&As[r * SA1 + c4] =
                *(const uint4*)&g_xt[(size_t)(m0 + r) * 128 + k0 + c4];
        }
#pragma unroll
        for (int i = 0; i < 4; i++) {
            int f = tid + i * 256;
            int k = f >> 5, n4 = (f & 31) * 4;
            *(uint4*)&Bs[k * SB1 + n4] =
                *(const uint4*)&g_W1t[(size_t)(k0 + k) * 512 + n0 + n4];
        }
        __syncthreads();
#pragma unroll
        for (int ks = 0; ks < 4; ks++) {
            int kc = ks * 8 + (lane & 3);
            uint32_t a[2][4];
            int r0 = warp_m * 32 + (lane >> 2);
#pragma unroll
            for (int mi = 0; mi < 2; mi++) {
                int r = r0 + mi * 16;
                a[mi][0] = As[r * SA1 + kc];
                a[mi][1] = As[(r + 8) * SA1 + kc];
                a[mi][2] = As[r * SA1 + kc + 4];
                a[mi][3] = As[(r + 8) * SA1 + kc + 4];
            }
#pragma unroll
            for (int nj = 0; nj < 8; nj++) {
                int n = warp_n * 64 + nj * 8 + (lane >> 2);
                uint32_t b0 = Bs[kc * SB1 + n];
                uint32_t b1 = Bs[(kc + 4) * SB1 + n];
                mma_tf32(acc[0][nj], a[0], b0, b1);
                mma_tf32(acc[1][nj], a[1], b0, b1);
            }
        }
        __syncthreads();
    }

    float* O = (n0 < 256) ? outL : outR;
    int nb = n0 & 255;
#pragma unroll
    for (int mi = 0; mi < 2; mi++) {
        int r = m0 + warp_m * 32 + mi * 16 + (lane >> 2);
#pragma unroll
        for (int nj = 0; nj < 8; nj++) {
            int nc = nb + warp_n * 64 + nj * 8 + (lane & 3) * 2;
            if (r < M)
                *(float2*)&O[(size_t)r * 256 + nc] = make_float2(acc[mi][nj][0], acc[mi][nj][1]);
            if (r + 8 < M)
                *(float2*)&O[(size_t)(r + 8) * 256 + nc] = make_float2(acc[mi][nj][2], acc[mi][nj][3]);
        }
    }
}

// ---------------- layer-1 fused single-pass online-softmax attention ----------------
__global__ __launch_bounds__(256) void k_attn1(const float* __restrict__ att,
                                               const float* __restrict__ b1, int N)
{
    int gt = blockIdx.x * blockDim.x + threadIdx.x;
    int w = gt >> 5, lane = gt & 31;
    if (w >= N) return;
    int beg = g_offs[w], end = g_offs[w + 1];

    const float4* pxr = (const float4*)g_xr1 + (size_t)w * 64 + lane * 2;
    float4 r0 = pxr[0], r1 = pxr[1];
    const float4* pa = (const float4*)att + lane * 2;
    float4 at0 = pa[0], at1 = pa[1];

    float mx = -1e30f, dn = 0.f;
    float c0 = 0, c1 = 0, c2 = 0, c3 = 0, c4 = 0, c5 = 0, c6 = 0, c7 = 0;

    for (int p = beg; p < end; p++) {
        int src = g_src[p];
        const float4* pl = (const float4*)g_xl1 + (size_t)src * 64 + lane * 2;
        float4 a0 = pl[0], a1 = pl[1];
        float v, s = 0.f;
        v = a0.x + r0.x; s += fmaxf(v, 0.2f * v) * at0.x;
        v = a0.y + r0.y; s += fmaxf(v, 0.2f * v) * at0.y;
        v = a0.z + r0.z; s += fmaxf(v, 0.2f * v) * at0.z;
        v = a0.w + r0.w; s += fmaxf(v, 0.2f * v) * at0.w;
        v = a1.x + r1.x; s += fmaxf(v, 0.2f * v) * at1.x;
        v = a1.y + r1.y; s += fmaxf(v, 0.2f * v) * at1.y;
        v = a1.z + r1.z; s += fmaxf(v, 0.2f * v) * at1.z;
        v = a1.w + r1.w; s += fmaxf(v, 0.2f * v) * at1.w;
        s += __shfl_xor_sync(0xffffffffu, s, 4);
        s += __shfl_xor_sync(0xffffffffu, s, 2);
        s += __shfl_xor_sync(0xffffffffu, s, 1);
        float mnew = fmaxf(mx, s);
        float sc = __expf(mx - mnew);
        float a = __expf(s - mnew);
        dn = dn * sc + a;
        c0 = c0 * sc + a * a0.x; c1 = c1 * sc + a * a0.y;
        c2 = c2 * sc + a * a0.z; c3 = c3 * sc + a * a0.w;
        c4 = c4 * sc + a * a1.x; c5 = c5 * sc + a * a1.y;
        c6 = c6 * sc + a * a1.z; c7 = c7 * sc + a * a1.w;
        mx = mnew;
    }
    float inv = 1.f / (dn + 1e-16f);
    const float4* pb = (const float4*)b1 + lane * 2;
    float4 bb0 = pb[0], bb1 = pb[1];
    ((float4*)g_h1)[(size_t)w * 64 + lane * 2 + 0] =
        make_float4(c0 * inv + bb0.x, c1 * inv + bb0.y, c2 * inv + bb0.z, c3 * inv + bb0.w);
    ((float4*)g_h1)[(size_t)w * 64 + lane * 2 + 1] =
        make_float4(c4 * inv + bb1.x, c5 * inv + bb1.y, c6 * inv + bb1.z, c7 * inv + bb1.w);
}

// ---------------- batch-norm stats ----------------
__global__ __launch_bounds__(256) void k_bnstats(int N)
{
    int c = threadIdx.x;
    int r0 = blockIdx.x * 128;
    int rend = min(r0 + 128, N);
    float s = 0.f, s2 = 0.f;
    for (int r = r0; r < rend; r++) {
        float v = g_h1[(size_t)r * 256 + c];
        s += v; s2 += v * v;
    }
    atomicAdd(&g_bn[c], s);
    atomicAdd(&g_bn[256 + c], s2);
}

__global__ void k_bnfin(const float* __restrict__ gamma,
                        const float* __restrict__ beta, int N)
{
    int c = threadIdx.x;
    float invN = 1.f / (float)N;
    float mu = g_bn[c] * invN;
    float var = g_bn[256 + c] * invN - mu * mu;
    float rs = rsqrtf(var + 1e-5f);
    float s = gamma[c] * rs;
    g_bns[c] = s;
    g_bnt[c] = beta[c] - s * mu;
}

// ---------------- layer-2 fused BN+ELU + tf32 GEMM ----------------
#define SA2 36
#define SB2 88
__global__ __launch_bounds__(256, 2) void k_gemm2_tc(float* __restrict__ xl2,
                                                     float* __restrict__ xr2, int M)
{
    __shared__ uint32_t As[128 * SA2];
    __shared__ uint32_t Bs[32 * SB2];
    int tid = threadIdx.x;
    int lane = tid & 31, wid = tid >> 5;
    int m0 = blockIdx.x * 128;
    float acc[10][4] = {};

    for (int k0 = 0; k0 < 256; k0 += 32) {
#pragma unroll
        for (int i = 0; i < 4; i++) {
            int f = tid + i * 256;
            int r = f >> 3, c4 = (f & 7) * 4;
            int gr = m0 + r;
            float4 v = make_float4(0.f, 0.f, 0.f, 0.f);
            if (gr < M) v = *(const float4*)&g_h1[(size_t)gr * 256 + k0 + c4];
            float4 s4 = *(const float4*)&g_bns[k0 + c4];
            float4 t4 = *(const float4*)&g_bnt[k0 + c4];
            float e0 = s4.x * v.x + t4.x; e0 = e0 > 0.f ? e0 : (__expf(e0) - 1.f);
            float e1 = s4.y * v.y + t4.y; e1 = e1 > 0.f ? e1 : (__expf(e1) - 1.f);
            float e2 = s4.z * v.z + t4.z; e2 = e2 > 0.f ? e2 : (__expf(e2) - 1.f);
            float e3 = s4.w * v.w + t4.w; e3 = e3 > 0.f ? e3 : (__expf(e3) - 1.f);
            uint4 u = make_uint4(f2tf32(e0), f2tf32(e1), f2tf32(e2), f2tf32(e3));
            *(uint4*)&As[r * SA2 + c4] = u;
        }
#pragma unroll
        for (int i = 0; i < 3; i++) {
            int f = tid + i * 256;
            if (f < 640) {
                int k = f / 20, n4 = (f % 20) * 4;
                *(uint4*)&Bs[k * SB2 + n4] =
                    *(const uint4*)&g_W2t[(size_t)(k0 + k) * 80 + n4];
            }
        }
        __syncthreads();
#pragma unroll
        for (int ks = 0; ks < 4; ks++) {
            int kc = ks * 8 + (lane & 3);
            int r = wid * 16 + (lane >> 2);
            uint32_t a[4];
            a[0] = As[r * SA2 + kc];
            a[1] = As[(r + 8) * SA2 + kc];
            a[2] = As[r * SA2 + kc + 4];
            a[3] = As[(r + 8) * SA2 + kc + 4];
#pragma unroll
            for (int nj = 0; nj < 10; nj++) {
                int n = nj * 8 + (lane >> 2);
                uint32_t b0 = Bs[kc * SB2 + n];
                uint32_t b1 = Bs[(kc + 4) * SB2 + n];
                mma_tf32(acc[nj], a, b0, b1);
            }
        }
        __syncthreads();
    }

    int r = m0 + wid * 16 + (lane >> 2);
#pragma unroll
    for (int nj = 0; nj < 10; nj++) {
        int col = nj * 8 + (lane & 3) * 2;
        float* O  = (col < 40) ? xl2 : xr2;
        int cc = (col < 40) ? col : col - 40;
        if (r < M)
            *(float2*)&O[(size_t)r * 40 + cc] = make_float2(acc[nj][0], acc[nj][1]);
        if (r + 8 < M)
            *(float2*)&O[(size_t)(r + 8) * 40 + cc] = make_float2(acc[nj][2], acc[nj][3]);
    }
}

// ---------------- layer-2 fused single-pass online-softmax attention ----------------
__global__ __launch_bounds__(256) void k_attn2(const float* __restrict__ att2,
                                               const float* __restrict__ b2,
                                               float* __restrict__ out, int N)
{
    int gt = blockIdx.x * blockDim.x + threadIdx.x;
    int w = gt >> 5, lane = gt & 31;
    if (w >= N) return;
    int beg = g_offs[w], end = g_offs[w + 1];
    int sub = lane >> 3, l8 = lane & 7;

    float xr[5], at[5];
#pragma unroll
    for (int j = 0; j < 5; j++) {
        int c = l8 * 5 + j;
        xr[j] = g_xr2[(size_t)w * 40 + c];
        at[j] = att2[c];
    }

    float mx = -1e30f, dn = 0.f;
    float acc[5] = {};

    for (int p0 = beg; p0 < end; p0 += 4) {
        int p = p0 + sub;
        bool valid = (p < end);
        int src = g_src[valid ? p : beg];
        float xls[5];
        float s = 0.f;
#pragma unroll
        for (int j = 0; j < 5; j++) {
            xls[j] = g_xl2[(size_t)src * 40 + l8 * 5 + j];
            float v = xls[j] + xr[j];
            s += fmaxf(v, 0.2f * v) * at[j];
        }
        s += __shfl_xor_sync(0xffffffffu, s, 4);
        s += __shfl_xor_sync(0xffffffffu, s, 2);
        s += __shfl_xor_sync(0xffffffffu, s, 1);
        if (!valid) s = -1e30f;
        float mnew = fmaxf(mx, s);
        float sc = __expf(mx - mnew);
        float a  = valid ? __expf(s - mnew) : 0.f;
        dn = dn * sc + a;
#pragma unroll
        for (int j = 0; j < 5; j++) acc[j] = acc[j] * sc + a * xls[j];
        mx = mnew;
    }

#pragma unroll
    for (int off = 8; off <= 16; off <<= 1) {
        float mo  = __shfl_xor_sync(0xffffffffu, mx, off);
        float dno = __shfl_xor_sync(0xffffffffu, dn, off);
        float ao[5];
#pragma unroll
        for (int j = 0; j < 5; j++) ao[j] = __shfl_xor_sync(0xffffffffu, acc[j], off);
        float m = fmaxf(mx, mo);
        float f1 = __expf(mx - m), f2 = __expf(mo - m);
        dn = dn * f1 + dno * f2;
#pragma unroll
        for (int j = 0; j < 5; j++) acc[j] = acc[j] * f1 + ao[j] * f2;
        mx = m;
    }

    float inv = 1.f / (dn + 1e-16f);
    if (sub == 0) {
#pragma unroll
        for (int j = 0; j < 5; j++) {
            int c = l8 * 5 + j;
            out[(size_t)w * 40 + c] = acc[j] * inv + b2[c];
        }
    }
}

// ---------------- host launcher (single stream) ----------------
extern "C" void kernel_launch(void* const* d_in, const int* in_sizes, int n_in,
                              void* d_out, int out_size)
{
    const float* x      = (const float*)d_in[0];
    const int*   ei     = (const int*)  d_in[1];
    const float* Wl1    = (const float*)d_in[2];
    const float* Wr1    = (const float*)d_in[3];
    const float* att1   = (const float*)d_in[4];
    const float* b1     = (const float*)d_in[5];
    const float* gamma1 = (const float*)d_in[6];
    const float* beta1  = (const float*)d_in[7];
    const float* Wl2    = (const float*)d_in[8];
    const float* Wr2    = (const float*)d_in[9];
    const float* att2   = (const float*)d_in[10];
    const float* b2     = (const float*)d_in[11];
    float* out = (float*)d_out;

    int N = in_sizes[0] / 128;
    int E = in_sizes[1] / 2;
    int ET = E + N;
    int G = (ET + 3) / 4;

    void *pxl1, *pxr1, *pxl2, *pxr2;
    cudaGetSymbolAddress(&pxl1, g_xl1);
    cudaGetSymbolAddress(&pxr1, g_xr1);
    cudaGetSymbolAddress(&pxl2, g_xl2);
    cudaGetSymbolAddress(&pxr2, g_xr2);

    // block-range sizes for k_pre
    int CB  = (G + 255) / 256;            // count blocks
    int W1B = (128 * 512) / 256;          // 256
    int W2B = (256 * 80 + 255) / 256;     // 80
    int XB  = (N * 32 + 255) / 256;       // x float4-convert blocks
    int PRE = CB + W1B + W2B + XB;

    k_zero<<<(N + 256) / 256, 256>>>(N);
    k_pre<<<PRE, 256>>>(ei, E, N, G, CB, W1B, W2B, x, Wl1, Wr1, Wl2, Wr2);
    k_scan<<<1, 1024>>>(N);

    int FB = CB;                          // fill blocks
    int GB = 4 * ((N + 127) / 128);       // gemm blocks (n-major flat)
    k_fill_gemm1<<<FB + GB, 256>>>(ei, E, N, G, FB, (float*)pxl1, (float*)pxr1, N);

    k_attn1<<<(N + 7) / 8, 256>>>(att1, b1, N);

    k_bnstats<<<(N + 127) / 128, 256>>>(N);
    k_bnfin<<<1, 256>>>(gamma1, beta1, N);

    k_gemm2_tc<<<(N + 127) / 128, 256>>>((float*)pxl2, (float*)pxr2, N);

    k_attn2<<<(N + 7) / 8, 256>>>(att2, b2, out, N);
}

// round 12
// speedup vs baseline: 1.3394x; 1.0498x over previous
#include <cuda_runtime.h>
#include <math.h>
#include <stdint.h>

#define D1 256
#define C2 40
#define MAXN 50176
#define MAXE 800000
#define MAXET (MAXE + MAXN)

// ---------------- static scratch (no runtime allocation) ----------------
__device__ float    g_xl1[(size_t)MAXN * D1];
__device__ float    g_xr1[(size_t)MAXN * D1];
__device__ float    g_h1 [(size_t)MAXN * D1];
__device__ float    g_xl2[(size_t)MAXN * C2];
__device__ float    g_xr2[(size_t)MAXN * C2];
__device__ uint32_t g_xt [(size_t)MAXN * 128];   // x pre-converted to tf32
__device__ int      g_counts[MAXN + 1];
__device__ int      g_offs  [MAXN + 1];
__device__ int      g_cursor[MAXN + 1];
__device__ int      g_src[MAXET];
__device__ float    g_bn[512];
__device__ uint32_t g_W1t[128 * 512];   // [Wl1 | Wr1] tf32
__device__ uint32_t g_W2t[256 * 80];    // [Wl2 | Wr2] tf32

__device__ __forceinline__ uint32_t f2tf32(float f) {
    uint32_t r;
    asm("cvt.rna.tf32.f32 %0, %1;" : "=r"(r) : "f"(f));
    return r;
}

__device__ __forceinline__ void mma_tf32(float c[4], const uint32_t a[4],
                                         uint32_t b0, uint32_t b1) {
    asm volatile(
        "mma.sync.aligned.m16n8k8.row.col.f32.tf32.tf32.f32 "
        "{%0,%1,%2,%3}, {%4,%5,%6,%7}, {%8,%9}, {%0,%1,%2,%3};"
        : "+f"(c[0]), "+f"(c[1]), "+f"(c[2]), "+f"(c[3])
        : "r"(a[0]), "r"(a[1]), "r"(a[2]), "r"(a[3]), "r"(b0), "r"(b1));
}

// ---------------- zero counts + bn accumulators ----------------
__global__ void k_zero(int n) {
    int i = blockIdx.x * blockDim.x + threadIdx.x;
    if (i <= n) g_counts[i] = 0;
    if (i < 512) g_bn[i] = 0.f;
}

// ---------------- fused pre-pass: count | w1cat | w2cat | x-convert ----------------
__global__ void k_pre(const int* __restrict__ ei, int E, int N, int G,
                      int CB, int W1B, int W2B,
                      const float* __restrict__ x,
                      const float* __restrict__ Wl1, const float* __restrict__ Wr1,
                      const float* __restrict__ Wl2, const float* __restrict__ Wr2)
{
    int b = blockIdx.x, tid = threadIdx.x;
    if (b < CB) {
        int t = b * 256 + tid;
        if (t >= G) return;
        int ET = E + N;
#pragma unroll
        for (int q = 0; q < 4; q++) {
            int i = t + q * G;
            if (i < ET) {
                int dst = (i < E) ? ei[E + i] : (i - E);
                atomicAdd(&g_counts[dst], 1);
            }
        }
    } else if (b < CB + W1B) {
        int i = (b - CB) * 256 + tid;
        int k = i >> 9, c = i & 511;
        float v = (c < 256) ? Wl1[k * 256 + c] : Wr1[k * 256 + (c - 256)];
        g_W1t[i] = f2tf32(v);
    } else if (b < CB + W1B + W2B) {
        int i = (b - CB - W1B) * 256 + tid;
        if (i < 256 * 80) {
            int k = i / 80, c = i % 80;
            float v = (c < 40) ? Wl2[k * 40 + c] : Wr2[k * 40 + (c - 40)];
            g_W2t[i] = f2tf32(v);
        }
    } else {
        int i = (b - CB - W1B - W2B) * 256 + tid;
        if (i < N * 32) {
            float4 v = ((const float4*)x)[i];
            ((uint4*)g_xt)[i] = make_uint4(f2tf32(v.x), f2tf32(v.y),
                                           f2tf32(v.z), f2tf32(v.w));
        }
    }
}

__global__ void k_scan(int n) {
    __shared__ int wsum[32];
    __shared__ int s_carry;
    int t = threadIdx.x, lane = t & 31, w = t >> 5;
    if (t == 0) s_carry = 0;
    __syncthreads();
    for (int base = 0; base < n; base += 1024) {
        int v = (base + t < n) ? g_counts[base + t] : 0;
        int s = v;
#pragma unroll
        for (int o = 1; o < 32; o <<= 1) {
            int y = __shfl_up_sync(0xffffffffu, s, o);
            if (lane >= o) s += y;
        }
        if (lane == 31) wsum[w] = s;
        __syncthreads();
        if (w == 0) {
            int ws = wsum[lane];
#pragma unroll
            for (int o = 1; o < 32; o <<= 1) {
                int y = __shfl_up_sync(0xffffffffu, ws, o);
                if (lane >= o) ws += y;
            }
            wsum[lane] = ws;
        }
        __syncthreads();
        int excl = s_carry + (w > 0 ? wsum[w - 1] : 0) + s - v;
        if (base + t < n) { g_offs[base + t] = excl; g_cursor[base + t] = excl; }
        int total = wsum[31];
        __syncthreads();
        if (t == 0) s_carry += total;
        __syncthreads();
    }
    if (t == 0) g_offs[n] = s_carry;
}

// ---------------- fused: CSR fill | layer-1 tf32 GEMM (512 thr, 32x32 warp tile) ----------------
#define SA1 36
#define SB1 136
__global__ __launch_bounds__(512, 2) void k_fill_gemm1(
    const int* __restrict__ ei, int E, int N, int G, int FB,
    float* __restrict__ outL, float* __restrict__ outR, int M)
{
    __shared__ uint32_t As[128 * SA1];
    __shared__ uint32_t Bs[32 * SB1];
    int tid = threadIdx.x;

    if (blockIdx.x < FB) {              // ---- CSR fill (512-thread blocks) ----
        int t = blockIdx.x * 512 + tid;
        if (t >= G) return;
        int ET = E + N;
#pragma unroll
        for (int q = 0; q < 4; q++) {
            int i = t + q * G;
            if (i < ET) {
                int src, dst;
                if (i < E) { src = ei[i]; dst = ei[E + i]; } else { src = dst = i - E; }
                int p = atomicAdd(&g_cursor[dst], 1);
                g_src[p] = src;
            }
        }
        return;
    }

    // ---- GEMM: C[M,512] = xt[M,128] @ W1t[128,512] ----
    int flat = blockIdx.x - FB;
    int n0 = (flat & 3) << 7;
    int m0 = (flat >> 2) << 7;
    int lane = tid & 31, wid = tid >> 5;      // 16 warps
    int warp_m = wid >> 2, warp_n = wid & 3;  // 4x4 grid, 32x32 warp tile
    float acc[2][4][4] = {};

    for (int k0 = 0; k0 < 128; k0 += 32) {
#pragma unroll
        for (int i = 0; i < 2; i++) {
            int f = tid + i * 512;              // 0..1023
            int r = f >> 3, c4 = (f & 7) * 4;
            *(uint4*)&As[r * SA1 + c4] =
                *(const uint4*)&g_xt[(size_t)(m0 + r) * 128 + k0 + c4];
        }
#pragma unroll
        for (int i = 0; i < 2; i++) {
            int f = tid + i * 512;
            int k = f >> 5, n4 = (f & 31) * 4;
            *(uint4*)&Bs[k * SB1 + n4] =
                *(const uint4*)&g_W1t[(size_t)(k0 + k) * 512 + n0 + n4];
        }
        __syncthreads();
#pragma unroll
        for (int ks = 0; ks < 4; ks++) {
            int kc = ks * 8 + (lane & 3);
            uint32_t a[2][4];
            int r0 = warp_m * 32 + (lane >> 2);
#pragma unroll
            for (int mi = 0; mi < 2; mi++) {
                int r = r0 + mi * 16;
                a[mi][0] = As[r * SA1 + kc];
                a[mi][1] = As[(r + 8) * SA1 + kc];
                a[mi][2] = As[r * SA1 + kc + 4];
                a[mi][3] = As[(r + 8) * SA1 + kc + 4];
            }
#pragma unroll
            for (int nj = 0; nj < 4; nj++) {
                int n = warp_n * 32 + nj * 8 + (lane >> 2);
                uint32_t b0 = Bs[kc * SB1 + n];
                uint32_t b1 = Bs[(kc + 4) * SB1 + n];
                mma_tf32(acc[0][nj], a[0], b0, b1);
                mma_tf32(acc[1][nj], a[1], b0, b1);
            }
        }
        __syncthreads();
    }

    float* O = (n0 < 256) ? outL : outR;
    int nb = n0 & 255;
#pragma unroll
    for (int mi = 0; mi < 2; mi++) {
        int r = m0 + warp_m * 32 + mi * 16 + (lane >> 2);
#pragma unroll
        for (int nj = 0; nj < 4; nj++) {
            int nc = nb + warp_n * 32 + nj * 8 + (lane & 3) * 2;
            if (r < M)
                *(float2*)&O[(size_t)r * 256 + nc] = make_float2(acc[mi][nj][0], acc[mi][nj][1]);
            if (r + 8 < M)
                *(float2*)&O[(size_t)(r + 8) * 256 + nc] = make_float2(acc[mi][nj][2], acc[mi][nj][3]);
        }
    }
}

// ---------------- layer-1 fused attention (2-edge ILP unroll) ----------------
__global__ __launch_bounds__(256) void k_attn1(const float* __restrict__ att,
                                               const float* __restrict__ b1, int N)
{
    int gt = blockIdx.x * blockDim.x + threadIdx.x;
    int w = gt >> 5, lane = gt & 31;
    if (w >= N) return;
    int beg = g_offs[w], end = g_offs[w + 1];

    const float4* pxr = (const float4*)g_xr1 + (size_t)w * 64 + lane * 2;
    float4 r0 = pxr[0], r1 = pxr[1];
    const float4* pa = (const float4*)att + lane * 2;
    float4 at0 = pa[0], at1 = pa[1];

    float mx = -1e30f, dn = 0.f;
    float c0 = 0, c1 = 0, c2 = 0, c3 = 0, c4 = 0, c5 = 0, c6 = 0, c7 = 0;

    int p = beg;
    for (; p + 2 <= end; p += 2) {
        int s0i = g_src[p], s1i = g_src[p + 1];
        const float4* p0 = (const float4*)g_xl1 + (size_t)s0i * 64 + lane * 2;
        const float4* p1 = (const float4*)g_xl1 + (size_t)s1i * 64 + lane * 2;
        float4 x0 = p0[0], x1 = p0[1];
        float4 y0 = p1[0], y1 = p1[1];
        float v, s0 = 0.f, s1 = 0.f;
        v = x0.x + r0.x; s0 += fmaxf(v, 0.2f * v) * at0.x;
        v = x0.y + r0.y; s0 += fmaxf(v, 0.2f * v) * at0.y;
        v = x0.z + r0.z; s0 += fmaxf(v, 0.2f * v) * at0.z;
        v = x0.w + r0.w; s0 += fmaxf(v, 0.2f * v) * at0.w;
        v = x1.x + r1.x; s0 += fmaxf(v, 0.2f * v) * at1.x;
        v = x1.y + r1.y; s0 += fmaxf(v, 0.2f * v) * at1.y;
        v = x1.z + r1.z; s0 += fmaxf(v, 0.2f * v) * at1.z;
        v = x1.w + r1.w; s0 += fmaxf(v, 0.2f * v) * at1.w;
        v = y0.x + r0.x; s1 += fmaxf(v, 0.2f * v) * at0.x;
        v = y0.y + r0.y; s1 += fmaxf(v, 0.2f * v) * at0.y;
        v = y0.z + r0.z; s1 += fmaxf(v, 0.2f * v) * at0.z;
        v = y0.w + r0.w; s1 += fmaxf(v, 0.2f * v) * at0.w;
        v = y1.x + r1.x; s1 += fmaxf(v, 0.2f * v) * at1.x;
        v = y1.y + r1.y; s1 += fmaxf(v, 0.2f * v) * at1.y;
        v = y1.z + r1.z; s1 += fmaxf(v, 0.2f * v) * at1.z;
        v = y1.w + r1.w; s1 += fmaxf(v, 0.2f * v) * at1.w;
        s0 += __shfl_xor_sync(0xffffffffu, s0, 4);
        s1 += __shfl_xor_sync(0xffffffffu, s1, 4);
        s0 += __shfl_xor_sync(0xffffffffu, s0, 2);
        s1 += __shfl_xor_sync(0xffffffffu, s1, 2);
        s0 += __shfl_xor_sync(0xffffffffu, s0, 1);
        s1 += __shfl_xor_sync(0xffffffffu, s1, 1);
        float mnew = fmaxf(mx, fmaxf(s0, s1));
        float sc = __expf(mx - mnew);
        float e0 = __expf(s0 - mnew);
        float e1 = __expf(s1 - mnew);
        dn = dn * sc + e0 + e1;
        c0 = c0 * sc + e0 * x0.x + e1 * y0.x;
        c1 = c1 * sc + e0 * x0.y + e1 * y0.y;
        c2 = c2 * sc + e0 * x0.z + e1 * y0.z;
        c3 = c3 * sc + e0 * x0.w + e1 * y0.w;
        c4 = c4 * sc + e0 * x1.x + e1 * y1.x;
        c5 = c5 * sc + e0 * x1.y + e1 * y1.y;
        c6 = c6 * sc + e0 * x1.z + e1 * y1.z;
        c7 = c7 * sc + e0 * x1.w + e1 * y1.w;
        mx = mnew;
    }
    if (p < end) {
        int src = g_src[p];
        const float4* pl = (const float4*)g_xl1 + (size_t)src * 64 + lane * 2;
        float4 a0 = pl[0], a1 = pl[1];
        float v, s = 0.f;
        v = a0.x + r0.x; s += fmaxf(v, 0.2f * v) * at0.x;
        v = a0.y + r0.y; s += fmaxf(v, 0.2f * v) * at0.y;
        v = a0.z + r0.z; s += fmaxf(v, 0.2f * v) * at0.z;
        v = a0.w + r0.w; s += fmaxf(v, 0.2f * v) * at0.w;
        v = a1.x + r1.x; s += fmaxf(v, 0.2f * v) * at1.x;
        v = a1.y + r1.y; s += fmaxf(v, 0.2f * v) * at1.y;
        v = a1.z + r1.z; s += fmaxf(v, 0.2f * v) * at1.z;
        v = a1.w + r1.w; s += fmaxf(v, 0.2f * v) * at1.w;
        s += __shfl_xor_sync(0xffffffffu, s, 4);
        s += __shfl_xor_sync(0xffffffffu, s, 2);
        s += __shfl_xor_sync(0xffffffffu, s, 1);
        float mnew = fmaxf(mx, s);
        float sc = __expf(mx - mnew);
        float a = __expf(s - mnew);
        dn = dn * sc + a;
        c0 = c0 * sc + a * a0.x; c1 = c1 * sc + a * a0.y;
        c2 = c2 * sc + a * a0.z; c3 = c3 * sc + a * a0.w;
        c4 = c4 * sc + a * a1.x; c5 = c5 * sc + a * a1.y;
        c6 = c6 * sc + a * a1.z; c7 = c7 * sc + a * a1.w;
        mx = mnew;
    }
    float inv = 1.f / (dn + 1e-16f);
    const float4* pb = (const float4*)b1 + lane * 2;
    float4 bb0 = pb[0], bb1 = pb[1];
    ((float4*)g_h1)[(size_t)w * 64 + lane * 2 + 0] =
        make_float4(c0 * inv + bb0.x, c1 * inv + bb0.y, c2 * inv + bb0.z, c3 * inv + bb0.w);
    ((float4*)g_h1)[(size_t)w * 64 + lane * 2 + 1] =
        make_float4(c4 * inv + bb1.x, c5 * inv + bb1.y, c6 * inv + bb1.z, c7 * inv + bb1.w);
}

// ---------------- batch-norm stats ----------------
__global__ __launch_bounds__(256) void k_bnstats(int N)
{
    int c = threadIdx.x;
    int r0 = blockIdx.x * 128;
    int rend = min(r0 + 128, N);
    float s = 0.f, s2 = 0.f;
    for (int r = r0; r < rend; r++) {
        float v = g_h1[(size_t)r * 256 + c];
        s += v; s2 += v * v;
    }
    atomicAdd(&g_bn[c], s);
    atomicAdd(&g_bn[256 + c], s2);
}

// ---------------- layer-2: BN-finalize prologue + BN+ELU + tf32 GEMM (64-row tiles) ----------------
#define SA2 36
#define SB2 88
__global__ __launch_bounds__(256) void k_gemm2_tc(
    const float* __restrict__ gamma, const float* __restrict__ beta,
    float* __restrict__ xl2, float* __restrict__ xr2, int M)
{
    __shared__ uint32_t As[64 * SA2];
    __shared__ uint32_t Bs[32 * SB2];
    __shared__ float sh_bns[256];
    __shared__ float sh_bnt[256];
    int tid = threadIdx.x;
    int lane = tid & 31, wid = tid >> 5;
    int warp_m = wid & 3, warp_n = wid >> 2;     // 4 m-warps x 2 n-warps
    int m0 = blockIdx.x * 64;
    float acc[5][4] = {};

    // BN finalize (per-block recompute; replaces k_bnfin)
    {
        float invN = 1.f / (float)M;
        float mu = g_bn[tid] * invN;
        float var = g_bn[256 + tid] * invN - mu * mu;
        float rs = rsqrtf(var + 1e-5f);
        float s = gamma[tid] * rs;
        sh_bns[tid] = s;
        sh_bnt[tid] = beta[tid] - s * mu;
    }
    __syncthreads();

    for (int k0 = 0; k0 < 256; k0 += 32) {
#pragma unroll
        for (int i = 0; i < 2; i++) {
            int f = tid + i * 256;              // 0..511
            int r = f >> 3, c4 = (f & 7) * 4;   // 64 rows x 8 float4
            int gr = m0 + r;
            float4 v = make_float4(0.f, 0.f, 0.f, 0.f);
            if (gr < M) v = *(const float4*)&g_h1[(size_t)gr * 256 + k0 + c4];
            float4 s4 = *(const float4*)&sh_bns[k0 + c4];
            float4 t4 = *(const float4*)&sh_bnt[k0 + c4];
            float e0 = s4.x * v.x + t4.x; e0 = e0 > 0.f ? e0 : (__expf(e0) - 1.f);
            float e1 = s4.y * v.y + t4.y; e1 = e1 > 0.f ? e1 : (__expf(e1) - 1.f);
            float e2 = s4.z * v.z + t4.z; e2 = e2 > 0.f ? e2 : (__expf(e2) - 1.f);
            float e3 = s4.w * v.w + t4.w; e3 = e3 > 0.f ? e3 : (__expf(e3) - 1.f);
            uint4 u = make_uint4(f2tf32(e0), f2tf32(e1), f2tf32(e2), f2tf32(e3));
            *(uint4*)&As[r * SA2 + c4] = u;
        }
#pragma unroll
        for (int i = 0; i < 3; i++) {
            int f = tid + i * 256;
            if (f < 640) {
                int k = f / 20, n4 = (f % 20) * 4;
                *(uint4*)&Bs[k * SB2 + n4] =
                    *(const uint4*)&g_W2t[(size_t)(k0 + k) * 80 + n4];
            }
        }
        __syncthreads();
#pragma unroll
        for (int ks = 0; ks < 4; ks++) {
            int kc = ks * 8 + (lane & 3);
            int r = warp_m * 16 + (lane >> 2);
            uint32_t a[4];
            a[0] = As[r * SA2 + kc];
            a[1] = As[(r + 8) * SA2 + kc];
            a[2] = As[r * SA2 + kc + 4];
            a[3] = As[(r + 8) * SA2 + kc + 4];
#pragma unroll
            for (int nj = 0; nj < 5; nj++) {
                int n = warp_n * 40 + nj * 8 + (lane >> 2);
                uint32_t b0 = Bs[kc * SB2 + n];
                uint32_t b1 = Bs[(kc + 4) * SB2 + n];
                mma_tf32(acc[nj], a, b0, b1);
            }
        }
        __syncthreads();
    }

    float* O = warp_n ? xr2 : xl2;
    int r = m0 + warp_m * 16 + (lane >> 2);
#pragma unroll
    for (int nj = 0; nj < 5; nj++) {
        int cc = nj * 8 + (lane & 3) * 2;
        if (r < M)
            *(float2*)&O[(size_t)r * 40 + cc] = make_float2(acc[nj][0], acc[nj][1]);
        if (r + 8 < M)
            *(float2*)&O[(size_t)(r + 8) * 40 + cc] = make_float2(acc[nj][2], acc[nj][3]);
    }
}

// ---------------- layer-2 fused single-pass online-softmax attention ----------------
__global__ __launch_bounds__(256) void k_attn2(const float* __restrict__ att2,
                                               const float* __restrict__ b2,
                                               float* __restrict__ out, int N)
{
    int gt = blockIdx.x * blockDim.x + threadIdx.x;
    int w = gt >> 5, lane = gt & 31;
    if (w >= N) return;
    int beg = g_offs[w], end = g_offs[w + 1];
    int sub = lane >> 3, l8 = lane & 7;

    float xr[5], at[5];
#pragma unroll
    for (int j = 0; j < 5; j++) {
        int c = l8 * 5 + j;
        xr[j] = g_xr2[(size_t)w * 40 + c];
        at[j] = att2[c];
    }

    float mx = -1e30f, dn = 0.f;
    float acc[5] = {};

    for (int p0 = beg; p0 < end; p0 += 4) {
        int p = p0 + sub;
        bool valid = (p < end);
        int src = g_src[valid ? p : beg];
        float xls[5];
        float s = 0.f;
#pragma unroll
        for (int j = 0; j < 5; j++) {
            xls[j] = g_xl2[(size_t)src * 40 + l8 * 5 + j];
            float v = xls[j] + xr[j];
            s += fmaxf(v, 0.2f * v) * at[j];
        }
        s += __shfl_xor_sync(0xffffffffu, s, 4);
        s += __shfl_xor_sync(0xffffffffu, s, 2);
        s += __shfl_xor_sync(0xffffffffu, s, 1);
        if (!valid) s = -1e30f;
        float mnew = fmaxf(mx, s);
        float sc = __expf(mx - mnew);
        float a  = valid ? __expf(s - mnew) : 0.f;
        dn = dn * sc + a;
#pragma unroll
        for (int j = 0; j < 5; j++) acc[j] = acc[j] * sc + a * xls[j];
        mx = mnew;
    }

#pragma unroll
    for (int off = 8; off <= 16; off <<= 1) {
        float mo  = __shfl_xor_sync(0xffffffffu, mx, off);
        float dno = __shfl_xor_sync(0xffffffffu, dn, off);
        float ao[5];
#pragma unroll
        for (int j = 0; j < 5; j++) ao[j] = __shfl_xor_sync(0xffffffffu, acc[j], off);
        float m = fmaxf(mx, mo);
        float f1 = __expf(mx - m), f2 = __expf(mo - m);
        dn = dn * f1 + dno * f2;
#pragma unroll
        for (int j = 0; j < 5; j++) acc[j] = acc[j] * f1 + ao[j] * f2;
        mx = m;
    }

    float inv = 1.f / (dn + 1e-16f);
    if (sub == 0) {
#pragma unroll
        for (int j = 0; j < 5; j++) {
            int c = l8 * 5 + j;
            out[(size_t)w * 40 + c] = acc[j] * inv + b2[c];
        }
    }
}

// ---------------- host launcher (single stream) ----------------
extern "C" void kernel_launch(void* const* d_in, const int* in_sizes, int n_in,
                              void* d_out, int out_size)
{
    const float* x      = (const float*)d_in[0];
    const int*   ei     = (const int*)  d_in[1];
    const float* Wl1    = (const float*)d_in[2];
    const float* Wr1    = (const float*)d_in[3];
    const float* att1   = (const float*)d_in[4];
    const float* b1     = (const float*)d_in[5];
    const float* gamma1 = (const float*)d_in[6];
    const float* beta1  = (const float*)d_in[7];
    const float* Wl2    = (const float*)d_in[8];
    const float* Wr2    = (const float*)d_in[9];
    const float* att2   = (const float*)d_in[10];
    const float* b2     = (const float*)d_in[11];
    float* out = (float*)d_out;

    int N = in_sizes[0] / 128;
    int E = in_sizes[1] / 2;
    int ET = E + N;
    int G = (ET + 3) / 4;

    void *pxl1, *pxr1, *pxl2, *pxr2;
    cudaGetSymbolAddress(&pxl1, g_xl1);
    cudaGetSymbolAddress(&pxr1, g_xr1);
    cudaGetSymbolAddress(&pxl2, g_xl2);
    cudaGetSymbolAddress(&pxr2, g_xr2);

    int CB  = (G + 255) / 256;
    int W1B = (128 * 512) / 256;
    int W2B = (256 * 80 + 255) / 256;
    int XB  = (N * 32 + 255) / 256;
    int PRE = CB + W1B + W2B + XB;

    k_zero<<<(N + 256) / 256, 256>>>(N);
    k_pre<<<PRE, 256>>>(ei, E, N, G, CB, W1B, W2B, x, Wl1, Wr1, Wl2, Wr2);
    k_scan<<<1, 1024>>>(N);

    int FB = (G + 511) / 512;
    int GB = 4 * ((N + 127) / 128);
    k_fill_gemm1<<<FB + GB, 512>>>(ei, E, N, G, FB, (float*)pxl1, (float*)pxr1, N);

    k_attn1<<<(N + 7) / 8, 256>>>(att1, b1, N);

    k_bnstats<<<(N + 127) / 128, 256>>>(N);

    k_gemm2_tc<<<(N + 63) / 64, 256>>>(gamma1, beta1, (float*)pxl2, (float*)pxr2, N);

    k_attn2<<<(N + 7) / 8, 256>>>(att2, b2, out, N);
}

// round 13
// speedup vs baseline: 1.3471x; 1.0057x over previous
#include <cuda_runtime.h>
#include <math.h>
#include <stdint.h>

#define D1 256
#define C2 40
#define MAXN 50176
#define MAXE 800000
#define MAXET (MAXE + MAXN)

// ---------------- static scratch (no runtime allocation) ----------------
__device__ float    g_xl1[(size_t)MAXN * D1];
__device__ float    g_xr1[(size_t)MAXN * D1];
__device__ float    g_h1 [(size_t)MAXN * D1];
__device__ float    g_xl2[(size_t)MAXN * C2];
__device__ float    g_xr2[(size_t)MAXN * C2];
__device__ uint32_t g_xt [(size_t)MAXN * 128];   // x pre-converted to tf32
__device__ int      g_counts[MAXN + 1];
__device__ int      g_offs  [MAXN + 1];
__device__ int      g_cursor[MAXN + 1];
__device__ int      g_src[MAXET];
__device__ float    g_bn[512];
__device__ uint32_t g_W1t[128 * 512];   // [Wl1 | Wr1] tf32
__device__ uint32_t g_W2t[256 * 80];    // [Wl2 | Wr2] tf32

__device__ __forceinline__ uint32_t f2tf32(float f) {
    uint32_t r;
    asm("cvt.rna.tf32.f32 %0, %1;" : "=r"(r) : "f"(f));
    return r;
}

__device__ __forceinline__ void mma_tf32(float c[4], const uint32_t a[4],
                                         uint32_t b0, uint32_t b1) {
    asm volatile(
        "mma.sync.aligned.m16n8k8.row.col.f32.tf32.tf32.f32 "
        "{%0,%1,%2,%3}, {%4,%5,%6,%7}, {%8,%9}, {%0,%1,%2,%3};"
        : "+f"(c[0]), "+f"(c[1]), "+f"(c[2]), "+f"(c[3])
        : "r"(a[0]), "r"(a[1]), "r"(a[2]), "r"(a[3]), "r"(b0), "r"(b1));
}

__device__ __forceinline__ void cp_async16(uint32_t smem_addr, const void* gptr) {
    asm volatile("cp.async.cg.shared.global [%0], [%1], 16;"
                 :: "r"(smem_addr), "l"(gptr));
}

// ---------------- zero counts + bn accumulators ----------------
__global__ void k_zero(int n) {
    int i = blockIdx.x * blockDim.x + threadIdx.x;
    if (i <= n) g_counts[i] = 0;
    if (i < 512) g_bn[i] = 0.f;
}

// ---------------- fused pre-pass: count | w1cat | w2cat | x-convert ----------------
__global__ void k_pre(const int* __restrict__ ei, int E, int N, int G,
                      int CB, int W1B, int W2B,
                      const float* __restrict__ x,
                      const float* __restrict__ Wl1, const float* __restrict__ Wr1,
                      const float* __restrict__ Wl2, const float* __restrict__ Wr2)
{
    int b = blockIdx.x, tid = threadIdx.x;
    if (b < CB) {
        int t = b * 256 + tid;
        if (t >= G) return;
        int ET = E + N;
#pragma unroll
        for (int q = 0; q < 4; q++) {
            int i = t + q * G;
            if (i < ET) {
                int dst = (i < E) ? ei[E + i] : (i - E);
                atomicAdd(&g_counts[dst], 1);
            }
        }
    } else if (b < CB + W1B) {
        int i = (b - CB) * 256 + tid;
        int k = i >> 9, c = i & 511;
        float v = (c < 256) ? Wl1[k * 256 + c] : Wr1[k * 256 + (c - 256)];
        g_W1t[i] = f2tf32(v);
    } else if (b < CB + W1B + W2B) {
        int i = (b - CB - W1B) * 256 + tid;
        if (i < 256 * 80) {
            int k = i / 80, c = i % 80;
            float v = (c < 40) ? Wl2[k * 40 + c] : Wr2[k * 40 + (c - 40)];
            g_W2t[i] = f2tf32(v);
        }
    } else {
        int i = (b - CB - W1B - W2B) * 256 + tid;
        if (i < N * 32) {
            float4 v = ((const float4*)x)[i];
            ((uint4*)g_xt)[i] = make_uint4(f2tf32(v.x), f2tf32(v.y),
                                           f2tf32(v.z), f2tf32(v.w));
        }
    }
}

__global__ void k_scan(int n) {
    __shared__ int wsum[32];
    __shared__ int s_carry;
    int t = threadIdx.x, lane = t & 31, w = t >> 5;
    if (t == 0) s_carry = 0;
    __syncthreads();
    for (int base = 0; base < n; base += 1024) {
        int v = (base + t < n) ? g_counts[base + t] : 0;
        int s = v;
#pragma unroll
        for (int o = 1; o < 32; o <<= 1) {
            int y = __shfl_up_sync(0xffffffffu, s, o);
            if (lane >= o) s += y;
        }
        if (lane == 31) wsum[w] = s;
        __syncthreads();
        if (w == 0) {
            int ws = wsum[lane];
#pragma unroll
            for (int o = 1; o < 32; o <<= 1) {
                int y = __shfl_up_sync(0xffffffffu, ws, o);
                if (lane >= o) ws += y;
            }
            wsum[lane] = ws;
        }
        __syncthreads();
        int excl = s_carry + (w > 0 ? wsum[w - 1] : 0) + s - v;
        if (base + t < n) { g_offs[base + t] = excl; g_cursor[base + t] = excl; }
        int total = wsum[31];
        __syncthreads();
        if (t == 0) s_carry += total;
        __syncthreads();
    }
    if (t == 0) g_offs[n] = s_carry;
}

// ---------------- fused: CSR fill | layer-1 tf32 GEMM (cp.async double buffer) ----------------
#define KC 16
#define SAW 20
#define SBW 136
__global__ __launch_bounds__(512, 2) void k_fill_gemm1(
    const int* __restrict__ ei, int E, int N, int G, int FB,
    float* __restrict__ outL, float* __restrict__ outR, int M)
{
    __shared__ uint32_t As[2][128 * SAW];
    __shared__ uint32_t Bs[2][KC * SBW];
    int tid = threadIdx.x;

    if (blockIdx.x < FB) {              // ---- CSR fill ----
        int t = blockIdx.x * 512 + tid;
        if (t >= G) return;
        int ET = E + N;
#pragma unroll
        for (int q = 0; q < 4; q++) {
            int i = t + q * G;
            if (i < ET) {
                int src, dst;
                if (i < E) { src = ei[i]; dst = ei[E + i]; } else { src = dst = i - E; }
                int p = atomicAdd(&g_cursor[dst], 1);
                g_src[p] = src;
            }
        }
        return;
    }

    // ---- GEMM: C[M,512] = xt[M,128] @ W1t[128,512] ----
    int flat = blockIdx.x - FB;
    int n0 = (flat & 3) << 7;
    int m0 = (flat >> 2) << 7;
    int lane = tid & 31, wid = tid >> 5;      // 16 warps
    int warp_m = wid >> 2, warp_n = wid & 3;  // 4x4 grid, 32x32 warp tile
    float acc[2][4][4] = {};

    // per-thread cp.async coordinates
    int ar = tid >> 2, aq = (tid & 3) * 4;    // A: row, word-quarter
    int bk = tid >> 5, bc = (tid & 31) * 4;   // B: k-row, col quarter
    const uint32_t* gA = &g_xt[(size_t)(m0 + ar) * 128 + aq];
    const uint32_t* gB = &g_W1t[(size_t)bk * 512 + n0 + bc];

    uint32_t sA0 = (uint32_t)__cvta_generic_to_shared(&As[0][ar * SAW + aq]);
    uint32_t sA1 = (uint32_t)__cvta_generic_to_shared(&As[1][ar * SAW + aq]);
    uint32_t sB0 = (uint32_t)__cvta_generic_to_shared(&Bs[0][bk * SBW + bc]);
    uint32_t sB1 = (uint32_t)__cvta_generic_to_shared(&Bs[1][bk * SBW + bc]);

    // prologue: chunk 0
    cp_async16(sA0, gA);
    cp_async16(sB0, gB);
    asm volatile("cp.async.commit_group;");

#pragma unroll
    for (int it = 0; it < 8; it++) {
        int buf = it & 1;
        if (it < 7) {
            int k0 = (it + 1) * KC;
            cp_async16(buf ? sA0 : sA1, gA + k0);
            cp_async16(buf ? sB0 : sB1, gB + (size_t)k0 * 512);
            asm volatile("cp.async.commit_group;");
            asm volatile("cp.async.wait_group 1;");
        } else {
            asm volatile("cp.async.wait_group 0;");
        }
        __syncthreads();

        const uint32_t* Ab = As[buf];
        const uint32_t* Bb = Bs[buf];
#pragma unroll
        for (int ks = 0; ks < 2; ks++) {
            int kc = ks * 8 + (lane & 3);
            uint32_t a[2][4];
            int r0 = warp_m * 32 + (lane >> 2);
#pragma unroll
            for (int mi = 0; mi < 2; mi++) {
                int r = r0 + mi * 16;
                a[mi][0] = Ab[r * SAW + kc];
                a[mi][1] = Ab[(r + 8) * SAW + kc];
                a[mi][2] = Ab[r * SAW + kc + 4];
                a[mi][3] = Ab[(r + 8) * SAW + kc + 4];
            }
#pragma unroll
            for (int nj = 0; nj < 4; nj++) {
                int n = warp_n * 32 + nj * 8 + (lane >> 2);
                uint32_t b0 = Bb[kc * SBW + n];
                uint32_t b1 = Bb[(kc + 4) * SBW + n];
                mma_tf32(acc[0][nj], a[0], b0, b1);
                mma_tf32(acc[1][nj], a[1], b0, b1);
            }
        }
        __syncthreads();
    }

    float* O = (n0 < 256) ? outL : outR;
    int nb = n0 & 255;
#pragma unroll
    for (int mi = 0; mi < 2; mi++) {
        int r = m0 + warp_m * 32 + mi * 16 + (lane >> 2);
#pragma unroll
        for (int nj = 0; nj < 4; nj++) {
            int nc = nb + warp_n * 32 + nj * 8 + (lane & 3) * 2;
            if (r < M)
                *(float2*)&O[(size_t)r * 256 + nc] = make_float2(acc[0][nj][0], acc[0][nj][1]);
            if (r + 8 < M)
                *(float2*)&O[(size_t)(r + 8) * 256 + nc] = make_float2(acc[0][nj][2], acc[0][nj][3]);
        }
        // second mi uses acc[1]
        if (mi == 0) continue;
    }
    // (rewritten explicitly below to avoid the loop-index/acc mismatch)
#pragma unroll
    for (int nj = 0; nj < 4; nj++) {
        int r = m0 + warp_m * 32 + 16 + (lane >> 2);
        int nc = nb + warp_n * 32 + nj * 8 + (lane & 3) * 2;
        if (r < M)
            *(float2*)&O[(size_t)r * 256 + nc] = make_float2(acc[1][nj][0], acc[1][nj][1]);
        if (r + 8 < M)
            *(float2*)&O[(size_t)(r + 8) * 256 + nc] = make_float2(acc[1][nj][2], acc[1][nj][3]);
    }
}

// ---------------- layer-1 fused attention (2-edge ILP unroll) ----------------
__global__ __launch_bounds__(256) void k_attn1(const float* __restrict__ att,
                                               const float* __restrict__ b1, int N)
{
    int gt = blockIdx.x * blockDim.x + threadIdx.x;
    int w = gt >> 5, lane = gt & 31;
    if (w >= N) return;
    int beg = g_offs[w], end = g_offs[w + 1];

    const float4* pxr = (const float4*)g_xr1 + (size_t)w * 64 + lane * 2;
    float4 r0 = pxr[0], r1 = pxr[1];
    const float4* pa = (const float4*)att + lane * 2;
    float4 at0 = pa[0], at1 = pa[1];

    float mx = -1e30f, dn = 0.f;
    float c0 = 0, c1 = 0, c2 = 0, c3 = 0, c4 = 0, c5 = 0, c6 = 0, c7 = 0;

    int p = beg;
    for (; p + 2 <= end; p += 2) {
        int s0i = g_src[p], s1i = g_src[p + 1];
        const float4* p0 = (const float4*)g_xl1 + (size_t)s0i * 64 + lane * 2;
        const float4* p1 = (const float4*)g_xl1 + (size_t)s1i * 64 + lane * 2;
        float4 x0 = p0[0], x1 = p0[1];
        float4 y0 = p1[0], y1 = p1[1];
        float v, s0 = 0.f, s1 = 0.f;
        v = x0.x + r0.x; s0 += fmaxf(v, 0.2f * v) * at0.x;
        v = x0.y + r0.y; s0 += fmaxf(v, 0.2f * v) * at0.y;
        v = x0.z + r0.z; s0 += fmaxf(v, 0.2f * v) * at0.z;
        v = x0.w + r0.w; s0 += fmaxf(v, 0.2f * v) * at0.w;
        v = x1.x + r1.x; s0 += fmaxf(v, 0.2f * v) * at1.x;
        v = x1.y + r1.y; s0 += fmaxf(v, 0.2f * v) * at1.y;
        v = x1.z + r1.z; s0 += fmaxf(v, 0.2f * v) * at1.z;
        v = x1.w + r1.w; s0 += fmaxf(v, 0.2f * v) * at1.w;
        v = y0.x + r0.x; s1 += fmaxf(v, 0.2f * v) * at0.x;
        v = y0.y + r0.y; s1 += fmaxf(v, 0.2f * v) * at0.y;
        v = y0.z + r0.z; s1 += fmaxf(v, 0.2f * v) * at0.z;
        v = y0.w + r0.w; s1 += fmaxf(v, 0.2f * v) * at0.w;
        v = y1.x + r1.x; s1 += fmaxf(v, 0.2f * v) * at1.x;
        v = y1.y + r1.y; s1 += fmaxf(v, 0.2f * v) * at1.y;
        v = y1.z + r1.z; s1 += fmaxf(v, 0.2f * v) * at1.z;
        v = y1.w + r1.w; s1 += fmaxf(v, 0.2f * v) * at1.w;
        s0 += __shfl_xor_sync(0xffffffffu, s0, 4);
        s1 += __shfl_xor_sync(0xffffffffu, s1, 4);
        s0 += __shfl_xor_sync(0xffffffffu, s0, 2);
        s1 += __shfl_xor_sync(0xffffffffu, s1, 2);
        s0 += __shfl_xor_sync(0xffffffffu, s0, 1);
        s1 += __shfl_xor_sync(0xffffffffu, s1, 1);
        float mnew = fmaxf(mx, fmaxf(s0, s1));
        float sc = __expf(mx - mnew);
        float e0 = __expf(s0 - mnew);
        float e1 = __expf(s1 - mnew);
        dn = dn * sc + e0 + e1;
        c0 = c0 * sc + e0 * x0.x + e1 * y0.x;
        c1 = c1 * sc + e0 * x0.y + e1 * y0.y;
        c2 = c2 * sc + e0 * x0.z + e1 * y0.z;
        c3 = c3 * sc + e0 * x0.w + e1 * y0.w;
        c4 = c4 * sc + e0 * x1.x + e1 * y1.x;
        c5 = c5 * sc + e0 * x1.y + e1 * y1.y;
        c6 = c6 * sc + e0 * x1.z + e1 * y1.z;
        c7 = c7 * sc + e0 * x1.w + e1 * y1.w;
        mx = mnew;
    }
    if (p < end) {
        int src = g_src[p];
        const float4* pl = (const float4*)g_xl1 + (size_t)src * 64 + lane * 2;
        float4 a0 = pl[0], a1 = pl[1];
        float v, s = 0.f;
        v = a0.x + r0.x; s += fmaxf(v, 0.2f * v) * at0.x;
        v = a0.y + r0.y; s += fmaxf(v, 0.2f * v) * at0.y;
        v = a0.z + r0.z; s += fmaxf(v, 0.2f * v) * at0.z;
        v = a0.w + r0.w; s += fmaxf(v, 0.2f * v) * at0.w;
        v = a1.x + r1.x; s += fmaxf(v, 0.2f * v) * at1.x;
        v = a1.y + r1.y; s += fmaxf(v, 0.2f * v) * at1.y;
        v = a1.z + r1.z; s += fmaxf(v, 0.2f * v) * at1.z;
        v = a1.w + r1.w; s += fmaxf(v, 0.2f * v) * at1.w;
        s += __shfl_xor_sync(0xffffffffu, s, 4);
        s += __shfl_xor_sync(0xffffffffu, s, 2);
        s += __shfl_xor_sync(0xffffffffu, s, 1);
        float mnew = fmaxf(mx, s);
        float sc = __expf(mx - mnew);
        float a = __expf(s - mnew);
        dn = dn * sc + a;
        c0 = c0 * sc + a * a0.x; c1 = c1 * sc + a * a0.y;
        c2 = c2 * sc + a * a0.z; c3 = c3 * sc + a * a0.w;
        c4 = c4 * sc + a * a1.x; c5 = c5 * sc + a * a1.y;
        c6 = c6 * sc + a * a1.z; c7 = c7 * sc + a * a1.w;
        mx = mnew;
    }
    float inv = 1.f / (dn + 1e-16f);
    const float4* pb = (const float4*)b1 + lane * 2;
    float4 bb0 = pb[0], bb1 = pb[1];
    ((float4*)g_h1)[(size_t)w * 64 + lane * 2 + 0] =
        make_float4(c0 * inv + bb0.x, c1 * inv + bb0.y, c2 * inv + bb0.z, c3 * inv + bb0.w);
    ((float4*)g_h1)[(size_t)w * 64 + lane * 2 + 1] =
        make_float4(c4 * inv + bb1.x, c5 * inv + bb1.y, c6 * inv + bb1.z, c7 * inv + bb1.w);
}

// ---------------- batch-norm stats ----------------
__global__ __launch_bounds__(256) void k_bnstats(int N)
{
    int c = threadIdx.x;
    int r0 = blockIdx.x * 128;
    int rend = min(r0 + 128, N);
    float s = 0.f, s2 = 0.f;
    for (int r = r0; r < rend; r++) {
        float v = g_h1[(size_t)r * 256 + c];
        s += v; s2 += v * v;
    }
    atomicAdd(&g_bn[c], s);
    atomicAdd(&g_bn[256 + c], s2);
}

// ---------------- layer-2: BN-finalize prologue + BN+ELU + tf32 GEMM (64-row tiles) ----------------
#define SA2 36
#define SB2 88
__global__ __launch_bounds__(256) void k_gemm2_tc(
    const float* __restrict__ gamma, const float* __restrict__ beta,
    float* __restrict__ xl2, float* __restrict__ xr2, int M)
{
    __shared__ uint32_t As2[64 * SA2];
    __shared__ uint32_t Bs2[32 * SB2];
    __shared__ float sh_bns[256];
    __shared__ float sh_bnt[256];
    int tid = threadIdx.x;
    int lane = tid & 31, wid = tid >> 5;
    int warp_m = wid & 3, warp_n = wid >> 2;
    int m0 = blockIdx.x * 64;
    float acc[5][4] = {};

    {
        float invN = 1.f / (float)M;
        float mu = g_bn[tid] * invN;
        float var = g_bn[256 + tid] * invN - mu * mu;
        float rs = rsqrtf(var + 1e-5f);
        float s = gamma[tid] * rs;
        sh_bns[tid] = s;
        sh_bnt[tid] = beta[tid] - s * mu;
    }
    __syncthreads();

    for (int k0 = 0; k0 < 256; k0 += 32) {
#pragma unroll
        for (int i = 0; i < 2; i++) {
            int f = tid + i * 256;
            int r = f >> 3, c4 = (f & 7) * 4;
            int gr = m0 + r;
            float4 v = make_float4(0.f, 0.f, 0.f, 0.f);
            if (gr < M) v = *(const float4*)&g_h1[(size_t)gr * 256 + k0 + c4];
            float4 s4 = *(const float4*)&sh_bns[k0 + c4];
            float4 t4 = *(const float4*)&sh_bnt[k0 + c4];
            float e0 = s4.x * v.x + t4.x; e0 = e0 > 0.f ? e0 : (__expf(e0) - 1.f);
            float e1 = s4.y * v.y + t4.y; e1 = e1 > 0.f ? e1 : (__expf(e1) - 1.f);
            float e2 = s4.z * v.z + t4.z; e2 = e2 > 0.f ? e2 : (__expf(e2) - 1.f);
            float e3 = s4.w * v.w + t4.w; e3 = e3 > 0.f ? e3 : (__expf(e3) - 1.f);
            uint4 u = make_uint4(f2tf32(e0), f2tf32(e1), f2tf32(e2), f2tf32(e3));
            *(uint4*)&As2[r * SA2 + c4] = u;
        }
#pragma unroll
        for (int i = 0; i < 3; i++) {
            int f = tid + i * 256;
            if (f < 640) {
                int k = f / 20, n4 = (f % 20) * 4;
                *(uint4*)&Bs2[k * SB2 + n4] =
                    *(const uint4*)&g_W2t[(size_t)(k0 + k) * 80 + n4];
            }
        }
        __syncthreads();
#pragma unroll
        for (int ks = 0; ks < 4; ks++) {
            int kc = ks * 8 + (lane & 3);
            int r = warp_m * 16 + (lane >> 2);
            uint32_t a[4];
            a[0] = As2[r * SA2 + kc];
            a[1] = As2[(r + 8) * SA2 + kc];
            a[2] = As2[r * SA2 + kc + 4];
            a[3] = As2[(r + 8) * SA2 + kc + 4];
#pragma unroll
            for (int nj = 0; nj < 5; nj++) {
                int n = warp_n * 40 + nj * 8 + (lane >> 2);
                uint32_t b0 = Bs2[kc * SB2 + n];
                uint32_t b1 = Bs2[(kc + 4) * SB2 + n];
                mma_tf32(acc[nj], a, b0, b1);
            }
        }
        __syncthreads();
    }

    float* O = warp_n ? xr2 : xl2;
    int r = m0 + warp_m * 16 + (lane >> 2);
#pragma unroll
    for (int nj = 0; nj < 5; nj++) {
        int cc = nj * 8 + (lane & 3) * 2;
        if (r < M)
            *(float2*)&O[(size_t)r * 40 + cc] = make_float2(acc[nj][0], acc[nj][1]);
        if (r + 8 < M)
            *(float2*)&O[(size_t)(r + 8) * 40 + cc] = make_float2(acc[nj][2], acc[nj][3]);
    }
}

// ---------------- layer-2 fused single-pass online-softmax attention ----------------
__global__ __launch_bounds__(256) void k_attn2(const float* __restrict__ att2,
                                               const float* __restrict__ b2,
                                               float* __restrict__ out, int N)
{
    int gt = blockIdx.x * blockDim.x + threadIdx.x;
    int w = gt >> 5, lane = gt & 31;
    if (w >= N) return;
    int beg = g_offs[w], end = g_offs[w + 1];
    int sub = lane >> 3, l8 = lane & 7;

    float xr[5], at[5];
#pragma unroll
    for (int j = 0; j < 5; j++) {
        int c = l8 * 5 + j;
        xr[j] = g_xr2[(size_t)w * 40 + c];
        at[j] = att2[c];
    }

    float mx = -1e30f, dn = 0.f;
    float acc[5] = {};

    for (int p0 = beg; p0 < end; p0 += 4) {
        int p = p0 + sub;
        bool valid = (p < end);
        int src = g_src[valid ? p : beg];
        float xls[5];
        float s = 0.f;
#pragma unroll
        for (int j = 0; j < 5; j++) {
            xls[j] = g_xl2[(size_t)src * 40 + l8 * 5 + j];
            float v = xls[j] + xr[j];
            s += fmaxf(v, 0.2f * v) * at[j];
        }
        s += __shfl_xor_sync(0xffffffffu, s, 4);
        s += __shfl_xor_sync(0xffffffffu, s, 2);
        s += __shfl_xor_sync(0xffffffffu, s, 1);
        if (!valid) s = -1e30f;
        float mnew = fmaxf(mx, s);
        float sc = __expf(mx - mnew);
        float a  = valid ? __expf(s - mnew) : 0.f;
        dn = dn * sc + a;
#pragma unroll
        for (int j = 0; j < 5; j++) acc[j] = acc[j] * sc + a * xls[j];
        mx = mnew;
    }

#pragma unroll
    for (int off = 8; off <= 16; off <<= 1) {
        float mo  = __shfl_xor_sync(0xffffffffu, mx, off);
        float dno = __shfl_xor_sync(0xffffffffu, dn, off);
        float ao[5];
#pragma unroll
        for (int j = 0; j < 5; j++) ao[j] = __shfl_xor_sync(0xffffffffu, acc[j], off);
        float m = fmaxf(mx, mo);
        float f1 = __expf(mx - m), f2 = __expf(mo - m);
        dn = dn * f1 + dno * f2;
#pragma unroll
        for (int j = 0; j < 5; j++) acc[j] = acc[j] * f1 + ao[j] * f2;
        mx = m;
    }

    float inv = 1.f / (dn + 1e-16f);
    if (sub == 0) {
#pragma unroll
        for (int j = 0; j < 5; j++) {
            int c = l8 * 5 + j;
            out[(size_t)w * 40 + c] = acc[j] * inv + b2[c];
        }
    }
}

// ---------------- host launcher (single stream) ----------------
extern "C" void kernel_launch(void* const* d_in, const int* in_sizes, int n_in,
                              void* d_out, int out_size)
{
    const float* x      = (const float*)d_in[0];
    const int*   ei     = (const int*)  d_in[1];
    const float* Wl1    = (const float*)d_in[2];
    const float* Wr1    = (const float*)d_in[3];
    const float* att1   = (const float*)d_in[4];
    const float* b1     = (const float*)d_in[5];
    const float* gamma1 = (const float*)d_in[6];
    const float* beta1  = (const float*)d_in[7];
    const float* Wl2    = (const float*)d_in[8];
    const float* Wr2    = (const float*)d_in[9];
    const float* att2   = (const float*)d_in[10];
    const float* b2     = (const float*)d_in[11];
    float* out = (float*)d_out;

    int N = in_sizes[0] / 128;
    int E = in_sizes[1] / 2;
    int ET = E + N;
    int G = (ET + 3) / 4;

    void *pxl1, *pxr1, *pxl2, *pxr2;
    cudaGetSymbolAddress(&pxl1, g_xl1);
    cudaGetSymbolAddress(&pxr1, g_xr1);
    cudaGetSymbolAddress(&pxl2, g_xl2);
    cudaGetSymbolAddress(&pxr2, g_xr2);

    int CB  = (G + 255) / 256;
    int W1B = (128 * 512) / 256;
    int W2B = (256 * 80 + 255) / 256;
    int XB  = (N * 32 + 255) / 256;
    int PRE = CB + W1B + W2B + XB;

    k_zero<<<(N + 256) / 256, 256>>>(N);
    k_pre<<<PRE, 256>>>(ei, E, N, G, CB, W1B, W2B, x, Wl1, Wr1, Wl2, Wr2);
    k_scan<<<1, 1024>>>(N);

    int FB = (G + 511) / 512;
    int GB = 4 * ((N + 127) / 128);
    k_fill_gemm1<<<FB + GB, 512>>>(ei, E, N, G, FB, (float*)pxl1, (float*)pxr1, N);

    k_attn1<<<(N + 7) / 8, 256>>>(att1, b1, N);

    k_bnstats<<<(N + 127) / 128, 256>>>(N);

    k_gemm2_tc<<<(N + 63) / 64, 256>>>(gamma1, beta1, (float*)pxl2, (float*)pxr2, N);

    k_attn2<<<(N + 7) / 8, 256>>>(att2, b2, out, N);
}